// round 6
// baseline (speedup 1.0000x reference)
#include <cuda_runtime.h>
#include <cuda_bf16.h>
#include <cuda_fp16.h>
#include <mma.h>
#include <math.h>
#include <cstdint>
#include <type_traits>

using namespace nvcuda;

#define Bb 2
#define NN 1024
#define DIM 1024
#define H 16
#define DH 64
#define INNER 1024
#define SCALE 0.125f

// ---------------- scratch (device globals; no allocation) ----------------
__device__ __half g_xn16[Bb * NN * DIM];
__device__ __half g_cn16[Bb * NN * DIM];
__device__ __half g_wqk16[DIM * INNER];
__device__ __half g_wcqk16[DIM * INNER];
__device__ __half g_wv16[DIM * INNER];
__device__ __half g_wcv16[DIM * INNER];
__device__ __half g_wout16[INNER * DIM];
__device__ __half g_wcout16[INNER * DIM];
__device__ __half g_qk16[Bb * NN * INNER];
__device__ __half g_cqk16[Bb * NN * INNER];
__device__ __half g_v16[Bb * NN * INNER];
__device__ __half g_cv16[Bb * NN * INNER];
__device__ float g_E[(size_t)Bb * H * NN * NN];          // 128 MB: exp(sim)
__device__ __half g_attn16[(size_t)Bb * H * NN * NN];    // 64 MB
__device__ __half g_cattn16[(size_t)Bb * H * NN * NN];   // 64 MB
__device__ float g_rs[Bb * H * NN];                      // row sums of exp
__device__ float g_cs[Bb * H * NN];                      // col sums of exp
__device__ __half g_o16[Bb * NN * INNER];
__device__ __half g_co16[Bb * NN * INNER];

// ---------------- cp.async helpers ----------------
__device__ __forceinline__ void cpasync16(void* s, const void* g) {
    unsigned int sa = (unsigned int)__cvta_generic_to_shared(s);
    asm volatile("cp.async.cg.shared.global [%0], [%1], 16;\n" ::"r"(sa), "l"(g));
}
__device__ __forceinline__ void cpasync_commit() {
    asm volatile("cp.async.commit_group;\n" ::);
}
template <int N>
__device__ __forceinline__ void cpasync_wait() {
    asm volatile("cp.async.wait_group %0;\n" ::"n"(N));
}

// ---------------- fp32 -> fp16 conversion (all 6 weights, one launch) ----------------
struct F2H6 { const float* s[6]; __half* d[6]; };
__global__ __launch_bounds__(256) void f2h6_kernel(F2H6 p) {
    int which = blockIdx.x >> 10;
    int i = ((blockIdx.x & 1023) * 256 + threadIdx.x) * 4;
    const float* s = p.s[which];
    __half* d = p.d[which];
    float4 f = *(const float4*)(s + i);
    *(__half2*)(d + i) = __floats2half2_rn(f.x, f.y);
    *(__half2*)(d + i + 2) = __floats2half2_rn(f.z, f.w);
}

// ---------------- zero the stat accumulators ----------------
__global__ __launch_bounds__(256) void zero_stats(float* RS, float* CS) {
    int i = blockIdx.x * 256 + threadIdx.x;  // grid 128 -> 32768
    RS[i] = 0.f;
    CS[i] = 0.f;
}

// ---------------- LayerNorm -> fp16 ----------------
__global__ __launch_bounds__(256) void ln_kernel(const float* __restrict__ X,
                                                 const float* __restrict__ G,
                                                 const float* __restrict__ Bt,
                                                 __half* __restrict__ O) {
    __shared__ float sred[8];
    __shared__ float sbc;
    int row = blockIdx.x;
    int tid = threadIdx.x;
    const float* x = X + (size_t)row * DIM;
    __half* o = O + (size_t)row * DIM;

    float v[4];
#pragma unroll
    for (int p = 0; p < 4; p++) v[p] = x[tid + 256 * p];

    float s = v[0] + v[1] + v[2] + v[3];
#pragma unroll
    for (int off = 16; off; off >>= 1) s += __shfl_xor_sync(0xffffffffu, s, off);
    int lane = tid & 31, w = tid >> 5;
    if (lane == 0) sred[w] = s;
    __syncthreads();
    if (tid == 0) {
        float t = 0.f;
#pragma unroll
        for (int k = 0; k < 8; k++) t += sred[k];
        sbc = t * (1.0f / DIM);
    }
    __syncthreads();
    float mu = sbc;
    __syncthreads();

    float d[4];
#pragma unroll
    for (int p = 0; p < 4; p++) d[p] = v[p] - mu;
    float s2 = d[0] * d[0] + d[1] * d[1] + d[2] * d[2] + d[3] * d[3];
#pragma unroll
    for (int off = 16; off; off >>= 1) s2 += __shfl_xor_sync(0xffffffffu, s2, off);
    if (lane == 0) sred[w] = s2;
    __syncthreads();
    if (tid == 0) {
        float t = 0.f;
#pragma unroll
        for (int k = 0; k < 8; k++) t += sred[k];
        sbc = rsqrtf(t * (1.0f / DIM) + 1e-5f);
    }
    __syncthreads();
    float rinv = sbc;

#pragma unroll
    for (int p = 0; p < 4; p++) {
        int idx = tid + 256 * p;
        o[idx] = __float2half(d[p] * rinv * G[idx] + Bt[idx]);
    }
}

// ---------------- pipelined wmma GEMM block (fp16 in, fp32 acc) ----------------
template <int BM, int BN, int BK, int WM, int WN,
          bool A_COL, bool B_COL, typename CT, bool BIAS, int STAGES>
__device__ __forceinline__ void gemm_db(
    const __half* __restrict__ A, int lda,
    const __half* __restrict__ B, int ldb,
    const float* __restrict__ bias,
    CT* __restrict__ C, int ldc,
    int K, float alpha, int m0, int n0, char* smem) {
    constexpr int AS_ROWS = A_COL ? BK : BM;
    constexpr int AS_COLS = (A_COL ? BM : BK) + 8;
    constexpr int BS_ROWS = B_COL ? BN : BK;
    constexpr int BS_COLS = (B_COL ? BK : BN) + 8;
    constexpr int A_ELE = AS_ROWS * AS_COLS;
    constexpr int B_ELE = BS_ROWS * BS_COLS;
    constexpr int STAGE = A_ELE + B_ELE;

    __half* sbase = (__half*)smem;

    constexpr int WARPS_N = BN / WN;
    constexpr int FM = WM / 16, FN = WN / 16;
    int tid = threadIdx.x;
    int wid = tid >> 5, lane = tid & 31;
    int wm = wid / WARPS_N, wn = wid % WARPS_N;

    wmma::fragment<wmma::accumulator, 16, 16, 16, float> acc[FM][FN];
#pragma unroll
    for (int i = 0; i < FM; i++)
#pragma unroll
        for (int j = 0; j < FN; j++) wmma::fill_fragment(acc[i][j], 0.0f);

    using ALay = typename std::conditional<A_COL, wmma::col_major, wmma::row_major>::type;
    using BLay = typename std::conditional<B_COL, wmma::col_major, wmma::row_major>::type;

    constexpr int AVEC = (A_COL ? BM : BK) / 8;
    constexpr int A_TOT = AS_ROWS * AVEC;
    constexpr int BVEC = (B_COL ? BK : BN) / 8;
    constexpr int B_TOT = BS_ROWS * BVEC;

    auto load_tile = [&](int k0, int buf) {
        __half* As = sbase + buf * STAGE;
        __half* Bs = As + A_ELE;
#pragma unroll
        for (int t = tid; t < A_TOT; t += 256) {
            int r = t / AVEC, c = (t % AVEC) * 8;
            const __half* src = A_COL
                ? A + (size_t)(k0 + r) * lda + m0 + c
                : A + (size_t)(m0 + r) * lda + k0 + c;
            cpasync16(&As[r * AS_COLS + c], src);
        }
#pragma unroll
        for (int t = tid; t < B_TOT; t += 256) {
            int r = t / BVEC, c = (t % BVEC) * 8;
            const __half* src = B_COL
                ? B + (size_t)(n0 + r) * ldb + k0 + c
                : B + (size_t)(k0 + r) * ldb + n0 + c;
            cpasync16(&Bs[r * BS_COLS + c], src);
        }
        cpasync_commit();
    };

    int KT = K / BK;
#pragma unroll
    for (int s = 0; s < STAGES - 1; s++)
        if (s < KT) load_tile(s * BK, s);

    for (int kt = 0; kt < KT; kt++) {
        cpasync_wait<STAGES - 2>();
        __syncthreads();
        int nxt = kt + STAGES - 1;
        if (nxt < KT) load_tile(nxt * BK, nxt % STAGES);
        else cpasync_commit();  // empty group keeps wait accounting correct

        __half* As = sbase + (kt % STAGES) * STAGE;
        __half* Bs = As + A_ELE;
#pragma unroll
        for (int kk = 0; kk < BK; kk += 16) {
            wmma::fragment<wmma::matrix_a, 16, 16, 16, __half, ALay> af[FM];
            wmma::fragment<wmma::matrix_b, 16, 16, 16, __half, BLay> bf[FN];
#pragma unroll
            for (int i = 0; i < FM; i++) {
                const __half* ap = A_COL
                    ? &As[kk * AS_COLS + wm * WM + i * 16]
                    : &As[(wm * WM + i * 16) * AS_COLS + kk];
                wmma::load_matrix_sync(af[i], ap, AS_COLS);
            }
#pragma unroll
            for (int j = 0; j < FN; j++) {
                const __half* bp = B_COL
                    ? &Bs[(wn * WN + j * 16) * BS_COLS + kk]
                    : &Bs[kk * BS_COLS + wn * WN + j * 16];
                wmma::load_matrix_sync(bf[j], bp, BS_COLS);
            }
#pragma unroll
            for (int i = 0; i < FM; i++)
#pragma unroll
                for (int j = 0; j < FN; j++)
                    wmma::mma_sync(acc[i][j], af[i], bf[j], acc[i][j]);
        }
    }
    __syncthreads();  // all compute done before epilogue reuses smem

    // epilogue: stage each 16x16 frag through smem, apply alpha/bias
    float* st = (float*)smem + wid * 256;
    int rr = lane >> 1, cc = (lane & 1) << 3;
#pragma unroll
    for (int i = 0; i < FM; i++)
#pragma unroll
        for (int j = 0; j < FN; j++) {
            wmma::store_matrix_sync(st, acc[i][j], 16, wmma::mem_row_major);
            __syncwarp();
            int grow = m0 + wm * WM + i * 16 + rr;
            int gcol = n0 + wn * WN + j * 16 + cc;
            float v[8];
#pragma unroll
            for (int t = 0; t < 8; t++) v[t] = st[rr * 16 + cc + t] * alpha;
            if (BIAS) {
#pragma unroll
                for (int t = 0; t < 8; t++) v[t] += bias[gcol + t];
            }
            if (std::is_same<CT, __half>::value) {
                alignas(16) __half hv[8];
#pragma unroll
                for (int t = 0; t < 8; t++) hv[t] = __float2half(v[t]);
                *(int4*)((__half*)C + (size_t)grow * ldc + gcol) = *(int4*)hv;
            } else {
                float* dst = (float*)C + (size_t)grow * ldc + gcol;
                *(float4*)dst = make_float4(v[0], v[1], v[2], v[3]);
                *(float4*)(dst + 4) = make_float4(v[4], v[5], v[6], v[7]);
            }
            __syncwarp();
        }
}

struct GemmP { const __half* A; const __half* B; const float* bias; void* C; };

// projections: 4 problems, M=2048 N=1024 K=1024, C fp16
// stage = (128*72 + 64*136) halfs = 17920 h = 35840 B; x2 stages = 71680 B (dynamic, 2 blocks/SM)
#define PROJ_SMEM 71680
__global__ __launch_bounds__(256) void proj4_kernel(GemmP p0, GemmP p1, GemmP p2, GemmP p3) {
    extern __shared__ __align__(16) char dsmem[];
    GemmP g;
    switch (blockIdx.z) {
        case 0: g = p0; break;
        case 1: g = p1; break;
        case 2: g = p2; break;
        default: g = p3; break;
    }
    gemm_db<128, 128, 64, 64, 32, false, false, __half, false, 2>(
        g.A, INNER, g.B, INNER, nullptr, (__half*)g.C, INNER,
        DIM, 1.0f, blockIdx.y * 128, blockIdx.x * 128, dsmem);
}

// output projections: 2 problems, bias, C fp32 (into d_out)
__global__ __launch_bounds__(256) void outproj2_kernel(GemmP p0, GemmP p1) {
    extern __shared__ __align__(16) char dsmem[];
    GemmP g = blockIdx.z ? p1 : p0;
    gemm_db<128, 128, 64, 64, 32, false, false, float, true, 2>(
        g.A, INNER, g.B, DIM, g.bias, (float*)g.C, DIM,
        INNER, 1.0f, blockIdx.y * 128, blockIdx.x * 128, dsmem);
}

// ---------------- sim: E = exp(scale * qk @ cqk^T) + fused row/col sums ----------------
__global__ __launch_bounds__(256) void sim_kernel(const __half* __restrict__ QK,
                                                  const __half* __restrict__ CQK,
                                                  float* __restrict__ E,
                                                  float* __restrict__ RS,
                                                  float* __restrict__ CS) {
    __shared__ __align__(16) __half As[128][72];
    __shared__ __align__(16) __half Bs[128][72];
    __shared__ float srow[128], scol[128];
    __shared__ float stf[8][256];
    int bh = blockIdx.z, b = bh >> 4, h = bh & 15;
    int i0 = blockIdx.y * 128, j0 = blockIdx.x * 128;
    const __half* A = QK + (size_t)b * NN * INNER + h * DH;
    const __half* Bm = CQK + (size_t)b * NN * INNER + h * DH;
    int tid = threadIdx.x, wid = tid >> 5, lane = tid & 31;

    if (tid < 128) { srow[tid] = 0.f; scol[tid] = 0.f; }
#pragma unroll
    for (int t = tid; t < 1024; t += 256) {
        int r = t >> 3, c = (t & 7) * 8;
        cpasync16(&As[r][c], A + (size_t)(i0 + r) * INNER + c);
    }
#pragma unroll
    for (int t = tid; t < 1024; t += 256) {
        int r = t >> 3, c = (t & 7) * 8;
        cpasync16(&Bs[r][c], Bm + (size_t)(j0 + r) * INNER + c);
    }
    cpasync_commit();
    cpasync_wait<0>();
    __syncthreads();

    int wm = wid >> 2, wn = wid & 3;  // 2 x 4 warps: WM=64, WN=32
    wmma::fragment<wmma::accumulator, 16, 16, 16, float> acc[4][2];
#pragma unroll
    for (int i = 0; i < 4; i++)
#pragma unroll
        for (int j = 0; j < 2; j++) wmma::fill_fragment(acc[i][j], 0.0f);

#pragma unroll
    for (int kk = 0; kk < 64; kk += 16) {
        wmma::fragment<wmma::matrix_a, 16, 16, 16, __half, wmma::row_major> af[4];
        wmma::fragment<wmma::matrix_b, 16, 16, 16, __half, wmma::col_major> bf[2];
#pragma unroll
        for (int i = 0; i < 4; i++)
            wmma::load_matrix_sync(af[i], &As[wm * 64 + i * 16][kk], 72);
#pragma unroll
        for (int j = 0; j < 2; j++)
            wmma::load_matrix_sync(bf[j], &Bs[wn * 32 + j * 16][kk], 72);
#pragma unroll
        for (int i = 0; i < 4; i++)
#pragma unroll
            for (int j = 0; j < 2; j++)
                wmma::mma_sync(acc[i][j], af[i], bf[j], acc[i][j]);
    }

    // epilogue: exp, store E, accumulate row/col sums
    float* st = stf[wid];
    int rr = lane >> 1, cc = (lane & 1) << 3;
    float rowp[4] = {0.f, 0.f, 0.f, 0.f};
    float colp[2][8] = {};
    float* Cp = E + ((size_t)bh << 20);
#pragma unroll
    for (int i = 0; i < 4; i++)
#pragma unroll
        for (int j = 0; j < 2; j++) {
            wmma::store_matrix_sync(st, acc[i][j], 16, wmma::mem_row_major);
            __syncwarp();
            int grow = i0 + wm * 64 + i * 16 + rr;
            int gcol = j0 + wn * 32 + j * 16 + cc;
            float e[8];
            float rsum = 0.f;
#pragma unroll
            for (int t = 0; t < 8; t++) {
                e[t] = __expf(st[rr * 16 + cc + t] * SCALE);
                rsum += e[t];
                colp[j][t] += e[t];
            }
            rowp[i] += rsum;
            float* dst = Cp + (size_t)grow * NN + gcol;
            *(float4*)dst = make_float4(e[0], e[1], e[2], e[3]);
            *(float4*)(dst + 4) = make_float4(e[4], e[5], e[6], e[7]);
            __syncwarp();
        }

#pragma unroll
    for (int i = 0; i < 4; i++)
        atomicAdd(&srow[wm * 64 + i * 16 + rr], rowp[i]);
#pragma unroll
    for (int j = 0; j < 2; j++)
#pragma unroll
        for (int t = 0; t < 8; t++)
            atomicAdd(&scol[wn * 32 + j * 16 + cc + t], colp[j][t]);
    __syncthreads();
    if (tid < 128) {
        atomicAdd(&RS[bh * NN + i0 + tid], srow[tid]);
        atomicAdd(&CS[bh * NN + j0 + tid], scol[tid]);
    }
}

// ---------------- dual normalize + talking heads -> fp16 (no exp; uses E) ----------------
__global__ __launch_bounds__(256) void softmax_th(const float* __restrict__ E,
                                                  const float* __restrict__ Wth,
                                                  const float* __restrict__ Wcth,
                                                  const float* __restrict__ RS,
                                                  const float* __restrict__ CS,
                                                  __half* __restrict__ ATT,
                                                  __half* __restrict__ CATT) {
    __shared__ float sW[256], sCW[256], srl[16];
    int b = blockIdx.z, i = blockIdx.y;
    int tid = threadIdx.x;
    int j = (blockIdx.x * 256 + tid) * 2;

    sW[tid] = Wth[tid];
    sCW[tid] = Wcth[tid];
    if (tid < 16) srl[tid] = 1.0f / RS[(b * 16 + tid) * NN + i];
    __syncthreads();

    float e0[16], e1[16], a0[16], a1[16];
#pragma unroll
    for (int h = 0; h < 16; h++) {
        float2 f = *(const float2*)&E[((size_t)(b * 16 + h) << 20) + (size_t)i * NN + j];
        e0[h] = f.x; e1[h] = f.y;
    }

    // row-normalized (attend over j)
#pragma unroll
    for (int h = 0; h < 16; h++) {
        a0[h] = e0[h] * srl[h];
        a1[h] = e1[h] * srl[h];
    }
#pragma unroll
    for (int g = 0; g < 16; g++) {
        float c0 = 0.f, c1 = 0.f;
#pragma unroll
        for (int h = 0; h < 16; h++) {
            float w = sW[g * 16 + h];
            c0 = fmaf(w, a0[h], c0);
            c1 = fmaf(w, a1[h], c1);
        }
        *(__half2*)&ATT[((size_t)(b * 16 + g) << 20) + (size_t)i * NN + j] =
            __floats2half2_rn(c0, c1);
    }

    // col-normalized (attend over i)
#pragma unroll
    for (int h = 0; h < 16; h++) {
        float2 cs = *(const float2*)&CS[(b * 16 + h) * NN + j];
        a0[h] = e0[h] * (1.0f / cs.x);
        a1[h] = e1[h] * (1.0f / cs.y);
    }
#pragma unroll
    for (int g = 0; g < 16; g++) {
        float c0 = 0.f, c1 = 0.f;
#pragma unroll
        for (int h = 0; h < 16; h++) {
            float w = sCW[g * 16 + h];
            c0 = fmaf(w, a0[h], c0);
            c1 = fmaf(w, a1[h], c1);
        }
        *(__half2*)&CATT[((size_t)(b * 16 + g) << 20) + (size_t)i * NN + j] =
            __floats2half2_rn(c0, c1);
    }
}

// ---------------- AV products, merged: z<32 -> out = attn'@cv ; z>=32 -> cout = cattn'^T@v
__global__ __launch_bounds__(256) void av_kernel(const __half* __restrict__ ATT,
                                                 const __half* __restrict__ CATT,
                                                 const __half* __restrict__ V,
                                                 const __half* __restrict__ CV,
                                                 __half* __restrict__ O,
                                                 __half* __restrict__ CO) {
    __shared__ __align__(16) char smem[29696];
    int z = blockIdx.z;
    if (z < 32) {
        int b = z >> 4, g = z & 15;
        gemm_db<128, 64, 32, 32, 32, false, false, __half, false, 2>(
            ATT + ((size_t)z << 20), NN, CV + ((size_t)b << 20) + g * DH, INNER,
            nullptr, O + ((size_t)b << 20) + g * DH, INNER,
            NN, 1.0f, blockIdx.y * 128, 0, smem);
    } else {
        int z2 = z - 32;
        int b = z2 >> 4, g = z2 & 15;
        gemm_db<128, 64, 32, 32, 32, true, false, __half, false, 2>(
            CATT + ((size_t)z2 << 20), NN, V + ((size_t)b << 20) + g * DH, INNER,
            nullptr, CO + ((size_t)b << 20) + g * DH, INNER,
            NN, 1.0f, blockIdx.y * 128, 0, smem);
    }
}

// ---------------- launch ----------------
extern "C" void kernel_launch(void* const* d_in, const int* in_sizes, int n_in,
                              void* d_out, int out_size) {
    const float* x = (const float*)d_in[0];
    const float* ctx = (const float*)d_in[1];
    const float* ln_g = (const float*)d_in[4];
    const float* ln_b = (const float*)d_in[5];
    const float* cln_g = (const float*)d_in[6];
    const float* cln_b = (const float*)d_in[7];
    const float* W_qk = (const float*)d_in[8];
    const float* W_cqk = (const float*)d_in[9];
    const float* W_v = (const float*)d_in[10];
    const float* W_cv = (const float*)d_in[11];
    const float* W_out = (const float*)d_in[12];
    const float* b_out = (const float*)d_in[13];
    const float* W_cout = (const float*)d_in[14];
    const float* b_cout = (const float*)d_in[15];
    const float* W_th = (const float*)d_in[16];
    const float* W_cth = (const float*)d_in[17];
    float* out = (float*)d_out;

    __half *xn16, *cn16, *wqk16, *wcqk16, *wv16, *wcv16, *wout16, *wcout16;
    __half *qk16, *cqk16, *v16, *cv16, *attn16, *cattn16, *o16, *co16;
    float *E, *rs, *cs;
    cudaGetSymbolAddress((void**)&xn16, g_xn16);
    cudaGetSymbolAddress((void**)&cn16, g_cn16);
    cudaGetSymbolAddress((void**)&wqk16, g_wqk16);
    cudaGetSymbolAddress((void**)&wcqk16, g_wcqk16);
    cudaGetSymbolAddress((void**)&wv16, g_wv16);
    cudaGetSymbolAddress((void**)&wcv16, g_wcv16);
    cudaGetSymbolAddress((void**)&wout16, g_wout16);
    cudaGetSymbolAddress((void**)&wcout16, g_wcout16);
    cudaGetSymbolAddress((void**)&qk16, g_qk16);
    cudaGetSymbolAddress((void**)&cqk16, g_cqk16);
    cudaGetSymbolAddress((void**)&v16, g_v16);
    cudaGetSymbolAddress((void**)&cv16, g_cv16);
    cudaGetSymbolAddress((void**)&attn16, g_attn16);
    cudaGetSymbolAddress((void**)&cattn16, g_cattn16);
    cudaGetSymbolAddress((void**)&o16, g_o16);
    cudaGetSymbolAddress((void**)&co16, g_co16);
    cudaGetSymbolAddress((void**)&E, g_E);
    cudaGetSymbolAddress((void**)&rs, g_rs);
    cudaGetSymbolAddress((void**)&cs, g_cs);

    cudaFuncSetAttribute(proj4_kernel, cudaFuncAttributeMaxDynamicSharedMemorySize, PROJ_SMEM);
    cudaFuncSetAttribute(outproj2_kernel, cudaFuncAttributeMaxDynamicSharedMemorySize, PROJ_SMEM);

    // 1) LayerNorms (fp16 out), weight conversions, stat zeroing
    ln_kernel<<<Bb * NN, 256>>>(x, ln_g, ln_b, xn16);
    ln_kernel<<<Bb * NN, 256>>>(ctx, cln_g, cln_b, cn16);
    {
        F2H6 p;
        p.s[0] = W_qk;   p.d[0] = wqk16;
        p.s[1] = W_cqk;  p.d[1] = wcqk16;
        p.s[2] = W_v;    p.d[2] = wv16;
        p.s[3] = W_cv;   p.d[3] = wcv16;
        p.s[4] = W_out;  p.d[4] = wout16;
        p.s[5] = W_cout; p.d[5] = wcout16;
        f2h6_kernel<<<6 * 1024, 256>>>(p);
    }
    zero_stats<<<128, 256>>>(rs, cs);

    // 2) 4 input projections (tensor cores, 2-stage BK=64 pipeline, 2 blocks/SM)
    {
        GemmP p0 = {xn16, wqk16, nullptr, qk16};
        GemmP p1 = {cn16, wcqk16, nullptr, cqk16};
        GemmP p2 = {xn16, wv16, nullptr, v16};
        GemmP p3 = {cn16, wcv16, nullptr, cv16};
        proj4_kernel<<<dim3(8, 16, 4), 256, PROJ_SMEM>>>(p0, p1, p2, p3);
    }

    // 3) sim -> E = exp(scale*sim) + fused row/col sums
    sim_kernel<<<dim3(8, 8, Bb * H), 256>>>(qk16, cqk16, E, rs, cs);

    // 4) dual normalize + talking heads (fp16 out)
    softmax_th<<<dim3(2, NN, Bb), 256>>>(E, W_th, W_cth, rs, cs, attn16, cattn16);

    // 5) AV products (merged)
    av_kernel<<<dim3(1, 8, 64), 256>>>(attn16, cattn16, v16, cv16, o16, co16);

    // 6) output projections (+bias) into d_out: [out | cout]
    {
        GemmP p0 = {o16, wout16, b_out, out};
        GemmP p1 = {co16, wcout16, b_cout, out + (size_t)Bb * NN * DIM};
        outproj2_kernel<<<dim3(8, 16, 2), 256, PROJ_SMEM>>>(p0, p1);
    }
}

// round 7
// speedup vs baseline: 1.0446x; 1.0446x over previous
#include <cuda_runtime.h>
#include <cuda_bf16.h>
#include <cuda_fp16.h>
#include <mma.h>
#include <math.h>
#include <cstdint>
#include <type_traits>

using namespace nvcuda;

#define Bb 2
#define NN 1024
#define DIM 1024
#define H 16
#define DH 64
#define INNER 1024
#define SCALE 0.125f

// ---------------- scratch (device globals; no allocation) ----------------
__device__ __half g_xn16[Bb * NN * DIM];
__device__ __half g_cn16[Bb * NN * DIM];
__device__ __half g_wqk16[DIM * INNER];
__device__ __half g_wcqk16[DIM * INNER];
__device__ __half g_wv16[DIM * INNER];
__device__ __half g_wcv16[DIM * INNER];
__device__ __half g_wout16[INNER * DIM];
__device__ __half g_wcout16[INNER * DIM];
__device__ __half g_qk16[Bb * NN * INNER];
__device__ __half g_cqk16[Bb * NN * INNER];
__device__ __half g_v16[Bb * NN * INNER];
__device__ __half g_cv16[Bb * NN * INNER];
__device__ __half g_E16[(size_t)Bb * H * NN * NN];       // 64 MB: exp(sim) fp16
__device__ __half g_attn16[(size_t)Bb * H * NN * NN];    // 64 MB
__device__ __half g_cattn16[(size_t)Bb * H * NN * NN];   // 64 MB
__device__ float g_rs[Bb * H * NN];                      // row sums of exp (fp32)
__device__ float g_cs[Bb * H * NN];                      // col sums of exp (fp32)
__device__ __half g_o16[Bb * NN * INNER];
__device__ __half g_co16[Bb * NN * INNER];

// ---------------- cp.async helpers ----------------
__device__ __forceinline__ void cpasync16(void* s, const void* g) {
    unsigned int sa = (unsigned int)__cvta_generic_to_shared(s);
    asm volatile("cp.async.cg.shared.global [%0], [%1], 16;\n" ::"r"(sa), "l"(g));
}
__device__ __forceinline__ void cpasync_commit() {
    asm volatile("cp.async.commit_group;\n" ::);
}
template <int N>
__device__ __forceinline__ void cpasync_wait() {
    asm volatile("cp.async.wait_group %0;\n" ::"n"(N));
}

// ---------------- fp32 -> fp16 conversion (all 6 weights, one launch) ----------------
struct F2H6 { const float* s[6]; __half* d[6]; };
__global__ __launch_bounds__(256) void f2h6_kernel(F2H6 p) {
    int which = blockIdx.x >> 10;
    int i = ((blockIdx.x & 1023) * 256 + threadIdx.x) * 4;
    const float* s = p.s[which];
    __half* d = p.d[which];
    float4 f = *(const float4*)(s + i);
    *(__half2*)(d + i) = __floats2half2_rn(f.x, f.y);
    *(__half2*)(d + i + 2) = __floats2half2_rn(f.z, f.w);
}

// ---------------- zero the stat accumulators ----------------
__global__ __launch_bounds__(256) void zero_stats(float* RS, float* CS) {
    int i = blockIdx.x * 256 + threadIdx.x;  // grid 128 -> 32768
    RS[i] = 0.f;
    CS[i] = 0.f;
}

// ---------------- LayerNorm -> fp16 ----------------
__global__ __launch_bounds__(256) void ln_kernel(const float* __restrict__ X,
                                                 const float* __restrict__ G,
                                                 const float* __restrict__ Bt,
                                                 __half* __restrict__ O) {
    __shared__ float sred[8];
    __shared__ float sbc;
    int row = blockIdx.x;
    int tid = threadIdx.x;
    const float* x = X + (size_t)row * DIM;
    __half* o = O + (size_t)row * DIM;

    float v[4];
#pragma unroll
    for (int p = 0; p < 4; p++) v[p] = x[tid + 256 * p];

    float s = v[0] + v[1] + v[2] + v[3];
#pragma unroll
    for (int off = 16; off; off >>= 1) s += __shfl_xor_sync(0xffffffffu, s, off);
    int lane = tid & 31, w = tid >> 5;
    if (lane == 0) sred[w] = s;
    __syncthreads();
    if (tid == 0) {
        float t = 0.f;
#pragma unroll
        for (int k = 0; k < 8; k++) t += sred[k];
        sbc = t * (1.0f / DIM);
    }
    __syncthreads();
    float mu = sbc;
    __syncthreads();

    float d[4];
#pragma unroll
    for (int p = 0; p < 4; p++) d[p] = v[p] - mu;
    float s2 = d[0] * d[0] + d[1] * d[1] + d[2] * d[2] + d[3] * d[3];
#pragma unroll
    for (int off = 16; off; off >>= 1) s2 += __shfl_xor_sync(0xffffffffu, s2, off);
    if (lane == 0) sred[w] = s2;
    __syncthreads();
    if (tid == 0) {
        float t = 0.f;
#pragma unroll
        for (int k = 0; k < 8; k++) t += sred[k];
        sbc = rsqrtf(t * (1.0f / DIM) + 1e-5f);
    }
    __syncthreads();
    float rinv = sbc;

#pragma unroll
    for (int p = 0; p < 4; p++) {
        int idx = tid + 256 * p;
        o[idx] = __float2half(d[p] * rinv * G[idx] + Bt[idx]);
    }
}

// ---------------- double-buffered wmma GEMM block (fp16 in, fp32 acc) — R4 version ----------------
template <int BM, int BN, int BK, int WM, int WN,
          bool A_COL, bool B_COL, typename CT, bool BIAS>
__device__ __forceinline__ void gemm_db(
    const __half* __restrict__ A, int lda,
    const __half* __restrict__ B, int ldb,
    const float* __restrict__ bias,
    CT* __restrict__ C, int ldc,
    int K, float alpha, int m0, int n0, char* smem) {
    constexpr int AS_ROWS = A_COL ? BK : BM;
    constexpr int AS_COLS = (A_COL ? BM : BK) + 8;
    constexpr int BS_ROWS = B_COL ? BN : BK;
    constexpr int BS_COLS = (B_COL ? BK : BN) + 8;
    constexpr int A_ELE = AS_ROWS * AS_COLS;
    constexpr int B_ELE = BS_ROWS * BS_COLS;
    constexpr int STAGE = A_ELE + B_ELE;

    __half* sbase = (__half*)smem;

    constexpr int WARPS_N = BN / WN;
    constexpr int FM = WM / 16, FN = WN / 16;
    int tid = threadIdx.x;
    int wid = tid >> 5, lane = tid & 31;
    int wm = wid / WARPS_N, wn = wid % WARPS_N;

    wmma::fragment<wmma::accumulator, 16, 16, 16, float> acc[FM][FN];
#pragma unroll
    for (int i = 0; i < FM; i++)
#pragma unroll
        for (int j = 0; j < FN; j++) wmma::fill_fragment(acc[i][j], 0.0f);

    using ALay = typename std::conditional<A_COL, wmma::col_major, wmma::row_major>::type;
    using BLay = typename std::conditional<B_COL, wmma::col_major, wmma::row_major>::type;

    constexpr int AVEC = (A_COL ? BM : BK) / 8;
    constexpr int A_TOT = AS_ROWS * AVEC;
    constexpr int BVEC = (B_COL ? BK : BN) / 8;
    constexpr int B_TOT = BS_ROWS * BVEC;

    auto load_tile = [&](int k0, int buf) {
        __half* As = sbase + buf * STAGE;
        __half* Bs = As + A_ELE;
#pragma unroll
        for (int t = tid; t < A_TOT; t += 256) {
            int r = t / AVEC, c = (t % AVEC) * 8;
            const __half* src = A_COL
                ? A + (size_t)(k0 + r) * lda + m0 + c
                : A + (size_t)(m0 + r) * lda + k0 + c;
            cpasync16(&As[r * AS_COLS + c], src);
        }
#pragma unroll
        for (int t = tid; t < B_TOT; t += 256) {
            int r = t / BVEC, c = (t % BVEC) * 8;
            const __half* src = B_COL
                ? B + (size_t)(n0 + r) * ldb + k0 + c
                : B + (size_t)(k0 + r) * ldb + n0 + c;
            cpasync16(&Bs[r * BS_COLS + c], src);
        }
        cpasync_commit();
    };

    int KT = K / BK;
    load_tile(0, 0);

    for (int kt = 0; kt < KT; kt++) {
        int cur = kt & 1;
        if (kt + 1 < KT) {
            load_tile((kt + 1) * BK, (kt + 1) & 1);
            cpasync_wait<1>();
        } else {
            cpasync_wait<0>();
        }
        __syncthreads();

        __half* As = sbase + cur * STAGE;
        __half* Bs = As + A_ELE;
#pragma unroll
        for (int kk = 0; kk < BK; kk += 16) {
            wmma::fragment<wmma::matrix_a, 16, 16, 16, __half, ALay> af[FM];
            wmma::fragment<wmma::matrix_b, 16, 16, 16, __half, BLay> bf[FN];
#pragma unroll
            for (int i = 0; i < FM; i++) {
                const __half* ap = A_COL
                    ? &As[kk * AS_COLS + wm * WM + i * 16]
                    : &As[(wm * WM + i * 16) * AS_COLS + kk];
                wmma::load_matrix_sync(af[i], ap, AS_COLS);
            }
#pragma unroll
            for (int j = 0; j < FN; j++) {
                const __half* bp = B_COL
                    ? &Bs[(wn * WN + j * 16) * BS_COLS + kk]
                    : &Bs[kk * BS_COLS + wn * WN + j * 16];
                wmma::load_matrix_sync(bf[j], bp, BS_COLS);
            }
#pragma unroll
            for (int i = 0; i < FM; i++)
#pragma unroll
                for (int j = 0; j < FN; j++)
                    wmma::mma_sync(acc[i][j], af[i], bf[j], acc[i][j]);
        }
        __syncthreads();
    }

    // epilogue: stage each 16x16 frag through smem, apply alpha/bias
    float* st = (float*)smem + wid * 256;
    int rr = lane >> 1, cc = (lane & 1) << 3;
#pragma unroll
    for (int i = 0; i < FM; i++)
#pragma unroll
        for (int j = 0; j < FN; j++) {
            wmma::store_matrix_sync(st, acc[i][j], 16, wmma::mem_row_major);
            __syncwarp();
            int grow = m0 + wm * WM + i * 16 + rr;
            int gcol = n0 + wn * WN + j * 16 + cc;
            float v[8];
#pragma unroll
            for (int t = 0; t < 8; t++) v[t] = st[rr * 16 + cc + t] * alpha;
            if (BIAS) {
#pragma unroll
                for (int t = 0; t < 8; t++) v[t] += bias[gcol + t];
            }
            if (std::is_same<CT, __half>::value) {
                alignas(16) __half hv[8];
#pragma unroll
                for (int t = 0; t < 8; t++) hv[t] = __float2half(v[t]);
                *(int4*)((__half*)C + (size_t)grow * ldc + gcol) = *(int4*)hv;
            } else {
                float* dst = (float*)C + (size_t)grow * ldc + gcol;
                *(float4*)dst = make_float4(v[0], v[1], v[2], v[3]);
                *(float4*)(dst + 4) = make_float4(v[4], v[5], v[6], v[7]);
            }
            __syncwarp();
        }
}

struct GemmP { const __half* A; const __half* B; const float* bias; void* C; };

// projections: 4 problems, M=2048 N=1024 K=1024, C fp16  (R4 config: BK=32, 2-stage, static smem)
__global__ __launch_bounds__(256) void proj4_kernel(GemmP p0, GemmP p1, GemmP p2, GemmP p3) {
    __shared__ __align__(16) char smem[37888];
    GemmP g;
    switch (blockIdx.z) {
        case 0: g = p0; break;
        case 1: g = p1; break;
        case 2: g = p2; break;
        default: g = p3; break;
    }
    gemm_db<128, 128, 32, 64, 32, false, false, __half, false>(
        g.A, INNER, g.B, INNER, nullptr, (__half*)g.C, INNER,
        DIM, 1.0f, blockIdx.y * 128, blockIdx.x * 128, smem);
}

// output projections: 2 problems, bias, C fp32 (into d_out)
__global__ __launch_bounds__(256) void outproj2_kernel(GemmP p0, GemmP p1) {
    __shared__ __align__(16) char smem[37888];
    GemmP g = blockIdx.z ? p1 : p0;
    gemm_db<128, 128, 32, 64, 32, false, false, float, true>(
        g.A, INNER, g.B, DIM, g.bias, (float*)g.C, DIM,
        INNER, 1.0f, blockIdx.y * 128, blockIdx.x * 128, smem);
}

// ---------------- sim: E16 = exp(scale * qk @ cqk^T), fused row/col sums ----------------
// K=64 resident; epilogue computes exp from fp32 acc, writes fp16 E, reduces sums.
// Staging buffer reuses the As region (no extra smem vs R4's sim).
__global__ __launch_bounds__(256) void sim_kernel(const __half* __restrict__ QK,
                                                  const __half* __restrict__ CQK,
                                                  __half* __restrict__ E,
                                                  float* __restrict__ RS,
                                                  float* __restrict__ CS) {
    __shared__ __align__(16) __half As[128][72];
    __shared__ __align__(16) __half Bs[128][72];
    __shared__ float srow[128], scol[128];
    int bh = blockIdx.z, b = bh >> 4, h = bh & 15;
    int i0 = blockIdx.y * 128, j0 = blockIdx.x * 128;
    const __half* A = QK + (size_t)b * NN * INNER + h * DH;
    const __half* Bm = CQK + (size_t)b * NN * INNER + h * DH;
    int tid = threadIdx.x, wid = tid >> 5, lane = tid & 31;

    if (tid < 128) { srow[tid] = 0.f; scol[tid] = 0.f; }
#pragma unroll
    for (int t = tid; t < 1024; t += 256) {
        int r = t >> 3, c = (t & 7) * 8;
        cpasync16(&As[r][c], A + (size_t)(i0 + r) * INNER + c);
    }
#pragma unroll
    for (int t = tid; t < 1024; t += 256) {
        int r = t >> 3, c = (t & 7) * 8;
        cpasync16(&Bs[r][c], Bm + (size_t)(j0 + r) * INNER + c);
    }
    cpasync_commit();
    cpasync_wait<0>();
    __syncthreads();

    int wm = wid >> 2, wn = wid & 3;  // 2 x 4 warps: WM=64, WN=32
    wmma::fragment<wmma::accumulator, 16, 16, 16, float> acc[4][2];
#pragma unroll
    for (int i = 0; i < 4; i++)
#pragma unroll
        for (int j = 0; j < 2; j++) wmma::fill_fragment(acc[i][j], 0.0f);

#pragma unroll
    for (int kk = 0; kk < 64; kk += 16) {
        wmma::fragment<wmma::matrix_a, 16, 16, 16, __half, wmma::row_major> af[4];
        wmma::fragment<wmma::matrix_b, 16, 16, 16, __half, wmma::col_major> bf[2];
#pragma unroll
        for (int i = 0; i < 4; i++)
            wmma::load_matrix_sync(af[i], &As[wm * 64 + i * 16][kk], 72);
#pragma unroll
        for (int j = 0; j < 2; j++)
            wmma::load_matrix_sync(bf[j], &Bs[wn * 32 + j * 16][kk], 72);
#pragma unroll
        for (int i = 0; i < 4; i++)
#pragma unroll
            for (int j = 0; j < 2; j++)
                wmma::mma_sync(acc[i][j], af[i], bf[j], acc[i][j]);
    }
    __syncthreads();  // all MMA smem reads done; As region is now free for staging

    float* st = (float*)&As[0][0] + wid * 256;  // 8 warps x 1KB = 8KB inside As (18KB)
    int rr = lane >> 1, cc = (lane & 1) << 3;
    float rowp[4] = {0.f, 0.f, 0.f, 0.f};
    float colp[2][8] = {};
    __half* Cp = E + ((size_t)bh << 20);
#pragma unroll
    for (int i = 0; i < 4; i++)
#pragma unroll
        for (int j = 0; j < 2; j++) {
            wmma::store_matrix_sync(st, acc[i][j], 16, wmma::mem_row_major);
            __syncwarp();
            int grow = i0 + wm * 64 + i * 16 + rr;
            int gcol = j0 + wn * 32 + j * 16 + cc;
            float e[8];
#pragma unroll
            for (int t = 0; t < 8; t++) {
                e[t] = __expf(st[rr * 16 + cc + t] * SCALE);
                rowp[i] += e[t];
                colp[j][t] += e[t];
            }
            alignas(16) __half2 hv[4];
#pragma unroll
            for (int t = 0; t < 4; t++) hv[t] = __floats2half2_rn(e[2 * t], e[2 * t + 1]);
            *(int4*)(Cp + (size_t)grow * NN + gcol) = *(int4*)hv;
            __syncwarp();
        }

#pragma unroll
    for (int i = 0; i < 4; i++)
        atomicAdd(&srow[wm * 64 + i * 16 + rr], rowp[i]);
#pragma unroll
    for (int j = 0; j < 2; j++)
#pragma unroll
        for (int t = 0; t < 8; t++)
            atomicAdd(&scol[wn * 32 + j * 16 + cc + t], colp[j][t]);
    __syncthreads();
    if (tid < 128) {
        atomicAdd(&RS[bh * NN + i0 + tid], srow[tid]);
        atomicAdd(&CS[bh * NN + j0 + tid], scol[tid]);
    }
}

// ---------------- dual normalize + talking heads -> fp16 (reads fp16 E, no exp) --------
__global__ __launch_bounds__(256) void softmax_th(const __half* __restrict__ E,
                                                  const float* __restrict__ Wth,
                                                  const float* __restrict__ Wcth,
                                                  const float* __restrict__ RS,
                                                  const float* __restrict__ CS,
                                                  __half* __restrict__ ATT,
                                                  __half* __restrict__ CATT) {
    __shared__ float sW[256], sCW[256], srl[16];
    int b = blockIdx.z, i = blockIdx.y;
    int tid = threadIdx.x;
    int j = (blockIdx.x * 256 + tid) * 2;

    sW[tid] = Wth[tid];
    sCW[tid] = Wcth[tid];
    if (tid < 16) srl[tid] = 1.0f / RS[(b * 16 + tid) * NN + i];
    __syncthreads();

    float e0[16], e1[16], a0[16], a1[16];
#pragma unroll
    for (int h = 0; h < 16; h++) {
        __half2 f = *(const __half2*)&E[((size_t)(b * 16 + h) << 20) + (size_t)i * NN + j];
        e0[h] = __low2float(f);
        e1[h] = __high2float(f);
    }

    // row-normalized (attend over j)
#pragma unroll
    for (int h = 0; h < 16; h++) {
        a0[h] = e0[h] * srl[h];
        a1[h] = e1[h] * srl[h];
    }
#pragma unroll
    for (int g = 0; g < 16; g++) {
        float c0 = 0.f, c1 = 0.f;
#pragma unroll
        for (int h = 0; h < 16; h++) {
            float w = sW[g * 16 + h];
            c0 = fmaf(w, a0[h], c0);
            c1 = fmaf(w, a1[h], c1);
        }
        *(__half2*)&ATT[((size_t)(b * 16 + g) << 20) + (size_t)i * NN + j] =
            __floats2half2_rn(c0, c1);
    }

    // col-normalized (attend over i)
#pragma unroll
    for (int h = 0; h < 16; h++) {
        float2 cs = *(const float2*)&CS[(b * 16 + h) * NN + j];
        a0[h] = e0[h] * (1.0f / cs.x);
        a1[h] = e1[h] * (1.0f / cs.y);
    }
#pragma unroll
    for (int g = 0; g < 16; g++) {
        float c0 = 0.f, c1 = 0.f;
#pragma unroll
        for (int h = 0; h < 16; h++) {
            float w = sCW[g * 16 + h];
            c0 = fmaf(w, a0[h], c0);
            c1 = fmaf(w, a1[h], c1);
        }
        *(__half2*)&CATT[((size_t)(b * 16 + g) << 20) + (size_t)i * NN + j] =
            __floats2half2_rn(c0, c1);
    }
}

// ---------------- AV GEMMs (R4-verbatim: two separate launches) ----------------
__global__ __launch_bounds__(256) void av_nn_wmma(const __half* __restrict__ ATT,
                                                  const __half* __restrict__ V,
                                                  __half* __restrict__ O) {
    __shared__ __align__(16) char smem[29696];
    int z = blockIdx.z;
    int b = z >> 4, g = z & 15;
    const __half* A = ATT + ((size_t)z << 20);
    const __half* Bm = V + ((size_t)b << 20) + g * DH;
    __half* C = O + ((size_t)b << 20) + g * DH;
    gemm_db<128, 64, 32, 32, 32, false, false, __half, false>(
        A, NN, Bm, INNER, nullptr, C, INNER,
        NN, 1.0f, blockIdx.y * 128, 0, smem);
}

__global__ __launch_bounds__(256) void av_tn_wmma(const __half* __restrict__ CATT,
                                                  const __half* __restrict__ V,
                                                  __half* __restrict__ O) {
    __shared__ __align__(16) char smem[26624];
    int z = blockIdx.z;
    int b = z >> 4, g = z & 15;
    const __half* A = CATT + ((size_t)z << 20);
    const __half* Bm = V + ((size_t)b << 20) + g * DH;
    __half* C = O + ((size_t)b << 20) + g * DH;
    gemm_db<128, 64, 32, 32, 32, true, false, __half, false>(
        A, NN, Bm, INNER, nullptr, C, INNER,
        NN, 1.0f, blockIdx.y * 128, 0, smem);
}

// ---------------- launch ----------------
extern "C" void kernel_launch(void* const* d_in, const int* in_sizes, int n_in,
                              void* d_out, int out_size) {
    const float* x = (const float*)d_in[0];
    const float* ctx = (const float*)d_in[1];
    const float* ln_g = (const float*)d_in[4];
    const float* ln_b = (const float*)d_in[5];
    const float* cln_g = (const float*)d_in[6];
    const float* cln_b = (const float*)d_in[7];
    const float* W_qk = (const float*)d_in[8];
    const float* W_cqk = (const float*)d_in[9];
    const float* W_v = (const float*)d_in[10];
    const float* W_cv = (const float*)d_in[11];
    const float* W_out = (const float*)d_in[12];
    const float* b_out = (const float*)d_in[13];
    const float* W_cout = (const float*)d_in[14];
    const float* b_cout = (const float*)d_in[15];
    const float* W_th = (const float*)d_in[16];
    const float* W_cth = (const float*)d_in[17];
    float* out = (float*)d_out;

    __half *xn16, *cn16, *wqk16, *wcqk16, *wv16, *wcv16, *wout16, *wcout16;
    __half *qk16, *cqk16, *v16, *cv16, *attn16, *cattn16, *o16, *co16, *E;
    float *rs, *cs;
    cudaGetSymbolAddress((void**)&xn16, g_xn16);
    cudaGetSymbolAddress((void**)&cn16, g_cn16);
    cudaGetSymbolAddress((void**)&wqk16, g_wqk16);
    cudaGetSymbolAddress((void**)&wcqk16, g_wcqk16);
    cudaGetSymbolAddress((void**)&wv16, g_wv16);
    cudaGetSymbolAddress((void**)&wcv16, g_wcv16);
    cudaGetSymbolAddress((void**)&wout16, g_wout16);
    cudaGetSymbolAddress((void**)&wcout16, g_wcout16);
    cudaGetSymbolAddress((void**)&qk16, g_qk16);
    cudaGetSymbolAddress((void**)&cqk16, g_cqk16);
    cudaGetSymbolAddress((void**)&v16, g_v16);
    cudaGetSymbolAddress((void**)&cv16, g_cv16);
    cudaGetSymbolAddress((void**)&attn16, g_attn16);
    cudaGetSymbolAddress((void**)&cattn16, g_cattn16);
    cudaGetSymbolAddress((void**)&o16, g_o16);
    cudaGetSymbolAddress((void**)&co16, g_co16);
    cudaGetSymbolAddress((void**)&E, g_E16);
    cudaGetSymbolAddress((void**)&rs, g_rs);
    cudaGetSymbolAddress((void**)&cs, g_cs);

    // 1) LayerNorms (fp16 out), weight conversions, stat zeroing
    ln_kernel<<<Bb * NN, 256>>>(x, ln_g, ln_b, xn16);
    ln_kernel<<<Bb * NN, 256>>>(ctx, cln_g, cln_b, cn16);
    {
        F2H6 p;
        p.s[0] = W_qk;   p.d[0] = wqk16;
        p.s[1] = W_cqk;  p.d[1] = wcqk16;
        p.s[2] = W_v;    p.d[2] = wv16;
        p.s[3] = W_cv;   p.d[3] = wcv16;
        p.s[4] = W_out;  p.d[4] = wout16;
        p.s[5] = W_cout; p.d[5] = wcout16;
        f2h6_kernel<<<6 * 1024, 256>>>(p);
    }
    zero_stats<<<128, 256>>>(rs, cs);

    // 2) 4 input projections (tensor cores, R4 config)
    {
        GemmP p0 = {xn16, wqk16, nullptr, qk16};
        GemmP p1 = {cn16, wcqk16, nullptr, cqk16};
        GemmP p2 = {xn16, wv16, nullptr, v16};
        GemmP p3 = {cn16, wcv16, nullptr, cv16};
        proj4_kernel<<<dim3(8, 16, 4), 256>>>(p0, p1, p2, p3);
    }

    // 3) sim -> E16 = exp(scale*sim) + fused row/col sums
    sim_kernel<<<dim3(8, 8, Bb * H), 256>>>(qk16, cqk16, E, rs, cs);

    // 4) dual normalize + talking heads (fp16 out)
    softmax_th<<<dim3(2, NN, Bb), 256>>>(E, W_th, W_cth, rs, cs, attn16, cattn16);

    // 5) AV products (R4-verbatim)
    av_nn_wmma<<<dim3(1, 8, Bb * H), 256>>>(attn16, cv16, o16);
    av_tn_wmma<<<dim3(1, 8, Bb * H), 256>>>(cattn16, v16, co16);

    // 6) output projections (+bias) into d_out: [out | cout]
    {
        GemmP p0 = {o16, wout16, b_out, out};
        GemmP p1 = {co16, wcout16, b_cout, out + (size_t)Bb * NN * DIM};
        outproj2_kernel<<<dim3(8, 16, 2), 256>>>(p0, p1);
    }
}

// round 8
// speedup vs baseline: 1.3677x; 1.3093x over previous
#include <cuda_runtime.h>
#include <cuda_bf16.h>
#include <cuda_fp16.h>
#include <mma.h>
#include <math.h>
#include <cstdint>
#include <type_traits>

using namespace nvcuda;

#define Bb 2
#define NN 1024
#define DIM 1024
#define H 16
#define DH 64
#define INNER 1024
#define SCALE 0.125f

// ---------------- scratch (device globals; no allocation) ----------------
__device__ __half g_xn16[Bb * NN * DIM];
__device__ __half g_cn16[Bb * NN * DIM];
__device__ __half g_wqk16[DIM * INNER];
__device__ __half g_wcqk16[DIM * INNER];
__device__ __half g_wv16[DIM * INNER];
__device__ __half g_wcv16[DIM * INNER];
__device__ __half g_wout16[INNER * DIM];
__device__ __half g_wcout16[INNER * DIM];
__device__ __half g_qk16[Bb * NN * INNER];
__device__ __half g_cqk16[Bb * NN * INNER];
__device__ __half g_v16[Bb * NN * INNER];
__device__ __half g_cv16[Bb * NN * INNER];
__device__ __half g_E16[(size_t)Bb * H * NN * NN];       // 64 MB: exp(sim) fp16
__device__ __half g_attn16[(size_t)Bb * H * NN * NN];    // 64 MB
__device__ __half g_cattn16[(size_t)Bb * H * NN * NN];   // 64 MB
__device__ float g_rs[Bb * H * NN];                      // row sums of exp
__device__ float g_cs[Bb * H * NN];                      // col sums of exp
__device__ __half g_o16[Bb * NN * INNER];
__device__ __half g_co16[Bb * NN * INNER];

// ---------------- cp.async helpers ----------------
__device__ __forceinline__ void cpasync16(void* s, const void* g) {
    unsigned int sa = (unsigned int)__cvta_generic_to_shared(s);
    asm volatile("cp.async.cg.shared.global [%0], [%1], 16;\n" ::"r"(sa), "l"(g));
}
__device__ __forceinline__ void cpasync_commit() {
    asm volatile("cp.async.commit_group;\n" ::);
}
template <int N>
__device__ __forceinline__ void cpasync_wait() {
    asm volatile("cp.async.wait_group %0;\n" ::"n"(N));
}

// ---------------- fp32 -> fp16 conversion (all 6 weights, one launch) ----------------
struct F2H6 { const float* s[6]; __half* d[6]; };
__global__ __launch_bounds__(256) void f2h6_kernel(F2H6 p) {
    int which = blockIdx.x >> 10;
    int i = ((blockIdx.x & 1023) * 256 + threadIdx.x) * 4;
    const float* s = p.s[which];
    __half* d = p.d[which];
    float4 f = *(const float4*)(s + i);
    *(__half2*)(d + i) = __floats2half2_rn(f.x, f.y);
    *(__half2*)(d + i + 2) = __floats2half2_rn(f.z, f.w);
}

// ---------------- LayerNorm -> fp16 ----------------
__global__ __launch_bounds__(256) void ln_kernel(const float* __restrict__ X,
                                                 const float* __restrict__ G,
                                                 const float* __restrict__ Bt,
                                                 __half* __restrict__ O) {
    __shared__ float sred[8];
    __shared__ float sbc;
    int row = blockIdx.x;
    int tid = threadIdx.x;
    const float* x = X + (size_t)row * DIM;
    __half* o = O + (size_t)row * DIM;

    float v[4];
#pragma unroll
    for (int p = 0; p < 4; p++) v[p] = x[tid + 256 * p];

    float s = v[0] + v[1] + v[2] + v[3];
#pragma unroll
    for (int off = 16; off; off >>= 1) s += __shfl_xor_sync(0xffffffffu, s, off);
    int lane = tid & 31, w = tid >> 5;
    if (lane == 0) sred[w] = s;
    __syncthreads();
    if (tid == 0) {
        float t = 0.f;
#pragma unroll
        for (int k = 0; k < 8; k++) t += sred[k];
        sbc = t * (1.0f / DIM);
    }
    __syncthreads();
    float mu = sbc;
    __syncthreads();

    float d[4];
#pragma unroll
    for (int p = 0; p < 4; p++) d[p] = v[p] - mu;
    float s2 = d[0] * d[0] + d[1] * d[1] + d[2] * d[2] + d[3] * d[3];
#pragma unroll
    for (int off = 16; off; off >>= 1) s2 += __shfl_xor_sync(0xffffffffu, s2, off);
    if (lane == 0) sred[w] = s2;
    __syncthreads();
    if (tid == 0) {
        float t = 0.f;
#pragma unroll
        for (int k = 0; k < 8; k++) t += sred[k];
        sbc = rsqrtf(t * (1.0f / DIM) + 1e-5f);
    }
    __syncthreads();
    float rinv = sbc;

#pragma unroll
    for (int p = 0; p < 4; p++) {
        int idx = tid + 256 * p;
        o[idx] = __float2half(d[p] * rinv * G[idx] + Bt[idx]);
    }
}

// ---------------- double-buffered wmma GEMM block (fp16 in, fp32 acc) ----------------
// DOEXP: epilogue applies exp(acc*alpha) instead of acc*alpha.
template <int BM, int BN, int BK, int WM, int WN,
          bool A_COL, bool B_COL, typename CT, bool BIAS, bool DOEXP>
__device__ __forceinline__ void gemm_db(
    const __half* __restrict__ A, int lda,
    const __half* __restrict__ B, int ldb,
    const float* __restrict__ bias,
    CT* __restrict__ C, int ldc,
    int K, float alpha, int m0, int n0, char* smem) {
    constexpr int AS_ROWS = A_COL ? BK : BM;
    constexpr int AS_COLS = (A_COL ? BM : BK) + 8;
    constexpr int BS_ROWS = B_COL ? BN : BK;
    constexpr int BS_COLS = (B_COL ? BK : BN) + 8;
    constexpr int A_ELE = AS_ROWS * AS_COLS;
    constexpr int B_ELE = BS_ROWS * BS_COLS;
    constexpr int STAGE = A_ELE + B_ELE;

    __half* sbase = (__half*)smem;

    constexpr int WARPS_N = BN / WN;
    constexpr int FM = WM / 16, FN = WN / 16;
    int tid = threadIdx.x;
    int wid = tid >> 5, lane = tid & 31;
    int wm = wid / WARPS_N, wn = wid % WARPS_N;

    wmma::fragment<wmma::accumulator, 16, 16, 16, float> acc[FM][FN];
#pragma unroll
    for (int i = 0; i < FM; i++)
#pragma unroll
        for (int j = 0; j < FN; j++) wmma::fill_fragment(acc[i][j], 0.0f);

    using ALay = typename std::conditional<A_COL, wmma::col_major, wmma::row_major>::type;
    using BLay = typename std::conditional<B_COL, wmma::col_major, wmma::row_major>::type;

    constexpr int AVEC = (A_COL ? BM : BK) / 8;
    constexpr int A_TOT = AS_ROWS * AVEC;
    constexpr int BVEC = (B_COL ? BK : BN) / 8;
    constexpr int B_TOT = BS_ROWS * BVEC;

    auto load_tile = [&](int k0, int buf) {
        __half* As = sbase + buf * STAGE;
        __half* Bs = As + A_ELE;
#pragma unroll
        for (int t = tid; t < A_TOT; t += 256) {
            int r = t / AVEC, c = (t % AVEC) * 8;
            const __half* src = A_COL
                ? A + (size_t)(k0 + r) * lda + m0 + c
                : A + (size_t)(m0 + r) * lda + k0 + c;
            cpasync16(&As[r * AS_COLS + c], src);
        }
#pragma unroll
        for (int t = tid; t < B_TOT; t += 256) {
            int r = t / BVEC, c = (t % BVEC) * 8;
            const __half* src = B_COL
                ? B + (size_t)(n0 + r) * ldb + k0 + c
                : B + (size_t)(k0 + r) * ldb + n0 + c;
            cpasync16(&Bs[r * BS_COLS + c], src);
        }
        cpasync_commit();
    };

    int KT = K / BK;
    load_tile(0, 0);

    for (int kt = 0; kt < KT; kt++) {
        int cur = kt & 1;
        if (kt + 1 < KT) {
            load_tile((kt + 1) * BK, (kt + 1) & 1);
            cpasync_wait<1>();
        } else {
            cpasync_wait<0>();
        }
        __syncthreads();

        __half* As = sbase + cur * STAGE;
        __half* Bs = As + A_ELE;
#pragma unroll
        for (int kk = 0; kk < BK; kk += 16) {
            wmma::fragment<wmma::matrix_a, 16, 16, 16, __half, ALay> af[FM];
            wmma::fragment<wmma::matrix_b, 16, 16, 16, __half, BLay> bf[FN];
#pragma unroll
            for (int i = 0; i < FM; i++) {
                const __half* ap = A_COL
                    ? &As[kk * AS_COLS + wm * WM + i * 16]
                    : &As[(wm * WM + i * 16) * AS_COLS + kk];
                wmma::load_matrix_sync(af[i], ap, AS_COLS);
            }
#pragma unroll
            for (int j = 0; j < FN; j++) {
                const __half* bp = B_COL
                    ? &Bs[(wn * WN + j * 16) * BS_COLS + kk]
                    : &Bs[kk * BS_COLS + wn * WN + j * 16];
                wmma::load_matrix_sync(bf[j], bp, BS_COLS);
            }
#pragma unroll
            for (int i = 0; i < FM; i++)
#pragma unroll
                for (int j = 0; j < FN; j++)
                    wmma::mma_sync(acc[i][j], af[i], bf[j], acc[i][j]);
        }
        __syncthreads();
    }

    // epilogue: stage each 16x16 frag through smem, apply alpha/exp/bias
    float* st = (float*)smem + wid * 256;
    int rr = lane >> 1, cc = (lane & 1) << 3;
#pragma unroll
    for (int i = 0; i < FM; i++)
#pragma unroll
        for (int j = 0; j < FN; j++) {
            wmma::store_matrix_sync(st, acc[i][j], 16, wmma::mem_row_major);
            __syncwarp();
            int grow = m0 + wm * WM + i * 16 + rr;
            int gcol = n0 + wn * WN + j * 16 + cc;
            float v[8];
#pragma unroll
            for (int t = 0; t < 8; t++) {
                float vv = st[rr * 16 + cc + t] * alpha;
                if (DOEXP) vv = __expf(vv);
                v[t] = vv;
            }
            if (BIAS) {
#pragma unroll
                for (int t = 0; t < 8; t++) v[t] += bias[gcol + t];
            }
            if (std::is_same<CT, __half>::value) {
                alignas(16) __half hv[8];
#pragma unroll
                for (int t = 0; t < 8; t++) hv[t] = __float2half(v[t]);
                *(int4*)((__half*)C + (size_t)grow * ldc + gcol) = *(int4*)hv;
            } else {
                float* dst = (float*)C + (size_t)grow * ldc + gcol;
                *(float4*)dst = make_float4(v[0], v[1], v[2], v[3]);
                *(float4*)(dst + 4) = make_float4(v[4], v[5], v[6], v[7]);
            }
            __syncwarp();
        }
}

struct GemmP { const __half* A; const __half* B; const float* bias; void* C; };

// projections: 4 problems, M=2048 N=1024 K=1024, C fp16  (R4 config)
__global__ __launch_bounds__(256) void proj4_kernel(GemmP p0, GemmP p1, GemmP p2, GemmP p3) {
    __shared__ __align__(16) char smem[37888];
    GemmP g;
    switch (blockIdx.z) {
        case 0: g = p0; break;
        case 1: g = p1; break;
        case 2: g = p2; break;
        default: g = p3; break;
    }
    gemm_db<128, 128, 32, 64, 32, false, false, __half, false, false>(
        g.A, INNER, g.B, INNER, nullptr, (__half*)g.C, INNER,
        DIM, 1.0f, blockIdx.y * 128, blockIdx.x * 128, smem);
}

// output projections: 2 problems, bias, C fp32 (into d_out)
__global__ __launch_bounds__(256) void outproj2_kernel(GemmP p0, GemmP p1) {
    __shared__ __align__(16) char smem[37888];
    GemmP g = blockIdx.z ? p1 : p0;
    gemm_db<128, 128, 32, 64, 32, false, false, float, true, false>(
        g.A, INNER, g.B, DIM, g.bias, (float*)g.C, DIM,
        INNER, 1.0f, blockIdx.y * 128, blockIdx.x * 128, smem);
}

// sim: E16 = exp(scale * qk @ cqk^T), R4 gemm_db shape with DOEXP + fp16 out
__global__ __launch_bounds__(256) void sim_wmma(const __half* __restrict__ QK,
                                                const __half* __restrict__ CQK,
                                                __half* __restrict__ E) {
    __shared__ __align__(16) char smem[40960];
    int bh = blockIdx.z;
    int b = bh >> 4, h = bh & 15;
    const __half* A = QK + (size_t)b * NN * INNER + h * DH;
    const __half* Bm = CQK + (size_t)b * NN * INNER + h * DH;
    __half* C = E + ((size_t)bh << 20);
    gemm_db<128, 128, 32, 64, 32, false, true, __half, false, true>(
        A, INNER, Bm, INNER, nullptr, C, NN,
        DH, SCALE, blockIdx.y * 128, blockIdx.x * 128, smem);
}

// ---------------- row sums of fp16 E (one warp per row, int4 loads) ----------------
__global__ __launch_bounds__(256) void rowsum(const __half* __restrict__ E,
                                              float* __restrict__ RS) {
    int warp = threadIdx.x >> 5, lane = threadIdx.x & 31;
    int r = blockIdx.x * 8 + warp;
    const int4* row = (const int4*)(E + (size_t)r * NN);  // 128 int4 per row

    float s = 0.f;
#pragma unroll
    for (int t = 0; t < 4; t++) {
        int4 v = row[lane + 32 * t];
        const __half2* h = (const __half2*)&v;
#pragma unroll
        for (int k = 0; k < 4; k++) {
            float2 f = __half22float2(h[k]);
            s += f.x + f.y;
        }
    }
#pragma unroll
    for (int off = 16; off; off >>= 1) s += __shfl_xor_sync(0xffffffffu, s, off);
    if (lane == 0) RS[r] = s;
}

// ---------------- col sums of fp16 E (half2 per thread, 4-way ILP) ----------------
__global__ __launch_bounds__(256) void colsum(const __half* __restrict__ E,
                                              float* __restrict__ CS) {
    int bh = blockIdx.y;
    int j2 = blockIdx.x * 256 + threadIdx.x;  // half2 column index (0..511)
    const __half2* base = (const __half2*)(E + ((size_t)bh << 20)) + j2;
    float2 a[4];
#pragma unroll
    for (int u = 0; u < 4; u++) a[u] = make_float2(0.f, 0.f);
    for (int i = 0; i < 256; i++) {
#pragma unroll
        for (int u = 0; u < 4; u++) {
            float2 f = __half22float2(base[(size_t)(i + 256 * u) * 512]);
            a[u].x += f.x;
            a[u].y += f.y;
        }
    }
    float2 r = make_float2(a[0].x + a[1].x + a[2].x + a[3].x,
                           a[0].y + a[1].y + a[2].y + a[3].y);
    *(float2*)&CS[bh * NN + j2 * 2] = r;
}

// ---------------- dual normalize + talking heads -> fp16 (reads fp16 E, no exp) --------
__global__ __launch_bounds__(256) void softmax_th(const __half* __restrict__ E,
                                                  const float* __restrict__ Wth,
                                                  const float* __restrict__ Wcth,
                                                  const float* __restrict__ RS,
                                                  const float* __restrict__ CS,
                                                  __half* __restrict__ ATT,
                                                  __half* __restrict__ CATT) {
    __shared__ float sW[256], sCW[256], srl[16];
    int b = blockIdx.z, i = blockIdx.y;
    int tid = threadIdx.x;
    int j = (blockIdx.x * 256 + tid) * 2;

    sW[tid] = Wth[tid];
    sCW[tid] = Wcth[tid];
    if (tid < 16) srl[tid] = 1.0f / RS[(b * 16 + tid) * NN + i];
    __syncthreads();

    float e0[16], e1[16], a0[16], a1[16];
#pragma unroll
    for (int h = 0; h < 16; h++) {
        __half2 f = *(const __half2*)&E[((size_t)(b * 16 + h) << 20) + (size_t)i * NN + j];
        e0[h] = __low2float(f);
        e1[h] = __high2float(f);
    }

    // row-normalized (attend over j)
#pragma unroll
    for (int h = 0; h < 16; h++) {
        a0[h] = e0[h] * srl[h];
        a1[h] = e1[h] * srl[h];
    }
#pragma unroll
    for (int g = 0; g < 16; g++) {
        float c0 = 0.f, c1 = 0.f;
#pragma unroll
        for (int h = 0; h < 16; h++) {
            float w = sW[g * 16 + h];
            c0 = fmaf(w, a0[h], c0);
            c1 = fmaf(w, a1[h], c1);
        }
        *(__half2*)&ATT[((size_t)(b * 16 + g) << 20) + (size_t)i * NN + j] =
            __floats2half2_rn(c0, c1);
    }

    // col-normalized (attend over i)
#pragma unroll
    for (int h = 0; h < 16; h++) {
        float2 cs = *(const float2*)&CS[(b * 16 + h) * NN + j];
        a0[h] = e0[h] * (1.0f / cs.x);
        a1[h] = e1[h] * (1.0f / cs.y);
    }
#pragma unroll
    for (int g = 0; g < 16; g++) {
        float c0 = 0.f, c1 = 0.f;
#pragma unroll
        for (int h = 0; h < 16; h++) {
            float w = sCW[g * 16 + h];
            c0 = fmaf(w, a0[h], c0);
            c1 = fmaf(w, a1[h], c1);
        }
        *(__half2*)&CATT[((size_t)(b * 16 + g) << 20) + (size_t)i * NN + j] =
            __floats2half2_rn(c0, c1);
    }
}

// ---------------- AV GEMMs (R4-verbatim: two separate launches) ----------------
__global__ __launch_bounds__(256) void av_nn_wmma(const __half* __restrict__ ATT,
                                                  const __half* __restrict__ V,
                                                  __half* __restrict__ O) {
    __shared__ __align__(16) char smem[29696];
    int z = blockIdx.z;
    int b = z >> 4, g = z & 15;
    const __half* A = ATT + ((size_t)z << 20);
    const __half* Bm = V + ((size_t)b << 20) + g * DH;
    __half* C = O + ((size_t)b << 20) + g * DH;
    gemm_db<128, 64, 32, 32, 32, false, false, __half, false, false>(
        A, NN, Bm, INNER, nullptr, C, INNER,
        NN, 1.0f, blockIdx.y * 128, 0, smem);
}

__global__ __launch_bounds__(256) void av_tn_wmma(const __half* __restrict__ CATT,
                                                  const __half* __restrict__ V,
                                                  __half* __restrict__ O) {
    __shared__ __align__(16) char smem[26624];
    int z = blockIdx.z;
    int b = z >> 4, g = z & 15;
    const __half* A = CATT + ((size_t)z << 20);
    const __half* Bm = V + ((size_t)b << 20) + g * DH;
    __half* C = O + ((size_t)b << 20) + g * DH;
    gemm_db<128, 64, 32, 32, 32, true, false, __half, false, false>(
        A, NN, Bm, INNER, nullptr, C, INNER,
        NN, 1.0f, blockIdx.y * 128, 0, smem);
}

// ---------------- launch ----------------
extern "C" void kernel_launch(void* const* d_in, const int* in_sizes, int n_in,
                              void* d_out, int out_size) {
    const float* x = (const float*)d_in[0];
    const float* ctx = (const float*)d_in[1];
    const float* ln_g = (const float*)d_in[4];
    const float* ln_b = (const float*)d_in[5];
    const float* cln_g = (const float*)d_in[6];
    const float* cln_b = (const float*)d_in[7];
    const float* W_qk = (const float*)d_in[8];
    const float* W_cqk = (const float*)d_in[9];
    const float* W_v = (const float*)d_in[10];
    const float* W_cv = (const float*)d_in[11];
    const float* W_out = (const float*)d_in[12];
    const float* b_out = (const float*)d_in[13];
    const float* W_cout = (const float*)d_in[14];
    const float* b_cout = (const float*)d_in[15];
    const float* W_th = (const float*)d_in[16];
    const float* W_cth = (const float*)d_in[17];
    float* out = (float*)d_out;

    __half *xn16, *cn16, *wqk16, *wcqk16, *wv16, *wcv16, *wout16, *wcout16;
    __half *qk16, *cqk16, *v16, *cv16, *attn16, *cattn16, *o16, *co16, *E;
    float *rs, *cs;
    cudaGetSymbolAddress((void**)&xn16, g_xn16);
    cudaGetSymbolAddress((void**)&cn16, g_cn16);
    cudaGetSymbolAddress((void**)&wqk16, g_wqk16);
    cudaGetSymbolAddress((void**)&wcqk16, g_wcqk16);
    cudaGetSymbolAddress((void**)&wv16, g_wv16);
    cudaGetSymbolAddress((void**)&wcv16, g_wcv16);
    cudaGetSymbolAddress((void**)&wout16, g_wout16);
    cudaGetSymbolAddress((void**)&wcout16, g_wcout16);
    cudaGetSymbolAddress((void**)&qk16, g_qk16);
    cudaGetSymbolAddress((void**)&cqk16, g_cqk16);
    cudaGetSymbolAddress((void**)&v16, g_v16);
    cudaGetSymbolAddress((void**)&cv16, g_cv16);
    cudaGetSymbolAddress((void**)&attn16, g_attn16);
    cudaGetSymbolAddress((void**)&cattn16, g_cattn16);
    cudaGetSymbolAddress((void**)&o16, g_o16);
    cudaGetSymbolAddress((void**)&co16, g_co16);
    cudaGetSymbolAddress((void**)&E, g_E16);
    cudaGetSymbolAddress((void**)&rs, g_rs);
    cudaGetSymbolAddress((void**)&cs, g_cs);

    // 1) LayerNorms (fp16 out) + weight conversions
    ln_kernel<<<Bb * NN, 256>>>(x, ln_g, ln_b, xn16);
    ln_kernel<<<Bb * NN, 256>>>(ctx, cln_g, cln_b, cn16);
    {
        F2H6 p;
        p.s[0] = W_qk;   p.d[0] = wqk16;
        p.s[1] = W_cqk;  p.d[1] = wcqk16;
        p.s[2] = W_v;    p.d[2] = wv16;
        p.s[3] = W_cv;   p.d[3] = wcv16;
        p.s[4] = W_out;  p.d[4] = wout16;
        p.s[5] = W_cout; p.d[5] = wcout16;
        f2h6_kernel<<<6 * 1024, 256>>>(p);
    }

    // 2) 4 input projections (R4 config; 4th launch -> ncu capture slot)
    {
        GemmP p0 = {xn16, wqk16, nullptr, qk16};
        GemmP p1 = {cn16, wcqk16, nullptr, cqk16};
        GemmP p2 = {xn16, wv16, nullptr, v16};
        GemmP p3 = {cn16, wcv16, nullptr, cv16};
        proj4_kernel<<<dim3(8, 16, 4), 256>>>(p0, p1, p2, p3);
    }

    // 3) sim -> E16 = exp(scale*sim) (fp16)
    sim_wmma<<<dim3(8, 8, Bb * H), 256>>>(qk16, cqk16, E);

    // 4) plain sums (no exp) over fp16 E
    rowsum<<<(Bb * H * NN) / 8, 256>>>(E, rs);
    colsum<<<dim3(2, Bb * H), 256>>>(E, cs);

    // 5) dual normalize + talking heads (fp16 out)
    softmax_th<<<dim3(2, NN, Bb), 256>>>(E, W_th, W_cth, rs, cs, attn16, cattn16);

    // 6) AV products
    av_nn_wmma<<<dim3(1, 8, Bb * H), 256>>>(attn16, cv16, o16);
    av_tn_wmma<<<dim3(1, 8, Bb * H), 256>>>(cattn16, v16, co16);

    // 7) output projections (+bias) into d_out: [out | cout]
    {
        GemmP p0 = {o16, wout16, b_out, out};
        GemmP p1 = {co16, wcout16, b_cout, out + (size_t)Bb * NN * DIM};
        outproj2_kernel<<<dim3(8, 16, 2), 256>>>(p0, p1);
    }
}

// round 11
// speedup vs baseline: 1.4670x; 1.0725x over previous
#include <cuda_runtime.h>
#include <cuda_bf16.h>
#include <cuda_fp16.h>
#include <mma.h>
#include <math.h>
#include <cstdint>
#include <type_traits>

using namespace nvcuda;

#define Bb 2
#define NN 1024
#define DIM 1024
#define H 16
#define DH 64
#define INNER 1024
#define SCALE 0.125f

// ---------------- scratch (device globals; no allocation) ----------------
__device__ __half g_xn16[Bb * NN * DIM];
__device__ __half g_cn16[Bb * NN * DIM];
__device__ __half g_wqk16[DIM * INNER];
__device__ __half g_wcqk16[DIM * INNER];
__device__ __half g_wv16[DIM * INNER];
__device__ __half g_wcv16[DIM * INNER];
__device__ __half g_wout16[INNER * DIM];
__device__ __half g_wcout16[INNER * DIM];
__device__ __half g_qk16[Bb * NN * INNER];
__device__ __half g_cqk16[Bb * NN * INNER];
__device__ __half g_v16[Bb * NN * INNER];
__device__ __half g_cv16[Bb * NN * INNER];
__device__ __half g_E16[(size_t)Bb * H * NN * NN];       // 64 MB: exp(sim) fp16
__device__ __half g_attn16[(size_t)Bb * H * NN * NN];    // 64 MB
__device__ __half g_cattn16[(size_t)Bb * H * NN * NN];   // 64 MB
__device__ float g_rs[Bb * H * NN];                      // row sums of exp
__device__ float g_cs[Bb * H * NN];                      // col sums of exp
__device__ __half g_o16[Bb * NN * INNER];
__device__ __half g_co16[Bb * NN * INNER];

// ---------------- cp.async helpers ----------------
__device__ __forceinline__ void cpasync16(void* s, const void* g) {
    unsigned int sa = (unsigned int)__cvta_generic_to_shared(s);
    asm volatile("cp.async.cg.shared.global [%0], [%1], 16;\n" ::"r"(sa), "l"(g));
}
__device__ __forceinline__ void cpasync_commit() {
    asm volatile("cp.async.commit_group;\n" ::);
}
template <int N>
__device__ __forceinline__ void cpasync_wait() {
    asm volatile("cp.async.wait_group %0;\n" ::"n"(N));
}

// ---------------- fp32 -> fp16 conversion (all 6 weights, one launch) ----------------
struct F2H6 { const float* s[6]; __half* d[6]; };
__global__ __launch_bounds__(256) void f2h6_kernel(F2H6 p) {
    int which = blockIdx.x >> 10;
    int i = ((blockIdx.x & 1023) * 256 + threadIdx.x) * 4;
    const float* s = p.s[which];
    __half* d = p.d[which];
    float4 f = *(const float4*)(s + i);
    *(__half2*)(d + i) = __floats2half2_rn(f.x, f.y);
    *(__half2*)(d + i + 2) = __floats2half2_rn(f.z, f.w);
}

// ---------------- zero CS (32768 floats) ----------------
__global__ __launch_bounds__(256) void zero_cs(float* CS) {
    int i = (blockIdx.x * 256 + threadIdx.x) * 4;
    *(float4*)(CS + i) = make_float4(0.f, 0.f, 0.f, 0.f);
}

// ---------------- LayerNorm -> fp16 ----------------
__global__ __launch_bounds__(256) void ln_kernel(const float* __restrict__ X,
                                                 const float* __restrict__ G,
                                                 const float* __restrict__ Bt,
                                                 __half* __restrict__ O) {
    __shared__ float sred[8];
    __shared__ float sbc;
    int row = blockIdx.x;
    int tid = threadIdx.x;
    const float* x = X + (size_t)row * DIM;
    __half* o = O + (size_t)row * DIM;

    float v[4];
#pragma unroll
    for (int p = 0; p < 4; p++) v[p] = x[tid + 256 * p];

    float s = v[0] + v[1] + v[2] + v[3];
#pragma unroll
    for (int off = 16; off; off >>= 1) s += __shfl_xor_sync(0xffffffffu, s, off);
    int lane = tid & 31, w = tid >> 5;
    if (lane == 0) sred[w] = s;
    __syncthreads();
    if (tid == 0) {
        float t = 0.f;
#pragma unroll
        for (int k = 0; k < 8; k++) t += sred[k];
        sbc = t * (1.0f / DIM);
    }
    __syncthreads();
    float mu = sbc;
    __syncthreads();

    float d[4];
#pragma unroll
    for (int p = 0; p < 4; p++) d[p] = v[p] - mu;
    float s2 = d[0] * d[0] + d[1] * d[1] + d[2] * d[2] + d[3] * d[3];
#pragma unroll
    for (int off = 16; off; off >>= 1) s2 += __shfl_xor_sync(0xffffffffu, s2, off);
    if (lane == 0) sred[w] = s2;
    __syncthreads();
    if (tid == 0) {
        float t = 0.f;
#pragma unroll
        for (int k = 0; k < 8; k++) t += sred[k];
        sbc = rsqrtf(t * (1.0f / DIM) + 1e-5f);
    }
    __syncthreads();
    float rinv = sbc;

#pragma unroll
    for (int p = 0; p < 4; p++) {
        int idx = tid + 256 * p;
        o[idx] = __float2half(d[p] * rinv * G[idx] + Bt[idx]);
    }
}

// ---------------- multi-stage pipelined wmma GEMM block (fp16 in, fp32 acc) ----------
// Pipeline: always-commit accounting; issue load for tile kt+STAGES-1, then
// wait<STAGES-1> (guarantees tile kt's group complete), then compute tile kt.
// Buffer (kt+STAGES-1)%STAGES == (kt-1)%STAGES was fully consumed at the end of
// iteration kt-1 (barrier).
template <int BM, int BN, int BK, int WM, int WN,
          bool A_COL, bool B_COL, typename CT, bool BIAS, bool DOEXP, int STAGES>
__device__ __forceinline__ void gemm_db(
    const __half* __restrict__ A, int lda,
    const __half* __restrict__ B, int ldb,
    const float* __restrict__ bias,
    CT* __restrict__ C, int ldc,
    int K, float alpha, int m0, int n0, char* smem) {
    constexpr int AS_ROWS = A_COL ? BK : BM;
    constexpr int AS_COLS = (A_COL ? BM : BK) + 8;
    constexpr int BS_ROWS = B_COL ? BN : BK;
    constexpr int BS_COLS = (B_COL ? BK : BN) + 8;
    constexpr int A_ELE = AS_ROWS * AS_COLS;
    constexpr int B_ELE = BS_ROWS * BS_COLS;
    constexpr int STAGE = A_ELE + B_ELE;

    __half* sbase = (__half*)smem;

    constexpr int WARPS_N = BN / WN;
    constexpr int FM = WM / 16, FN = WN / 16;
    int tid = threadIdx.x;
    int wid = tid >> 5, lane = tid & 31;
    int wm = wid / WARPS_N, wn = wid % WARPS_N;

    wmma::fragment<wmma::accumulator, 16, 16, 16, float> acc[FM][FN];
#pragma unroll
    for (int i = 0; i < FM; i++)
#pragma unroll
        for (int j = 0; j < FN; j++) wmma::fill_fragment(acc[i][j], 0.0f);

    using ALay = typename std::conditional<A_COL, wmma::col_major, wmma::row_major>::type;
    using BLay = typename std::conditional<B_COL, wmma::col_major, wmma::row_major>::type;

    constexpr int AVEC = (A_COL ? BM : BK) / 8;
    constexpr int A_TOT = AS_ROWS * AVEC;
    constexpr int BVEC = (B_COL ? BK : BN) / 8;
    constexpr int B_TOT = BS_ROWS * BVEC;

    auto load_tile = [&](int k0, int buf) {
        __half* As = sbase + buf * STAGE;
        __half* Bs = As + A_ELE;
#pragma unroll
        for (int t = tid; t < A_TOT; t += 256) {
            int r = t / AVEC, c = (t % AVEC) * 8;
            const __half* src = A_COL
                ? A + (size_t)(k0 + r) * lda + m0 + c
                : A + (size_t)(m0 + r) * lda + k0 + c;
            cpasync16(&As[r * AS_COLS + c], src);
        }
#pragma unroll
        for (int t = tid; t < B_TOT; t += 256) {
            int r = t / BVEC, c = (t % BVEC) * 8;
            const __half* src = B_COL
                ? B + (size_t)(n0 + r) * ldb + k0 + c
                : B + (size_t)(k0 + r) * ldb + n0 + c;
            cpasync16(&Bs[r * BS_COLS + c], src);
        }
        cpasync_commit();
    };

    int KT = K / BK;
#pragma unroll
    for (int s = 0; s < STAGES - 1; s++) {
        if (s < KT) load_tile(s * BK, s);
        else cpasync_commit();
    }

    for (int kt = 0; kt < KT; kt++) {
        int nxt = kt + STAGES - 1;
        if (nxt < KT) load_tile(nxt * BK, nxt % STAGES);
        else cpasync_commit();
        cpasync_wait<STAGES - 1>();
        __syncthreads();

        __half* As = sbase + (kt % STAGES) * STAGE;
        __half* Bs = As + A_ELE;
#pragma unroll
        for (int kk = 0; kk < BK; kk += 16) {
            wmma::fragment<wmma::matrix_a, 16, 16, 16, __half, ALay> af[FM];
            wmma::fragment<wmma::matrix_b, 16, 16, 16, __half, BLay> bf[FN];
#pragma unroll
            for (int i = 0; i < FM; i++) {
                const __half* ap = A_COL
                    ? &As[kk * AS_COLS + wm * WM + i * 16]
                    : &As[(wm * WM + i * 16) * AS_COLS + kk];
                wmma::load_matrix_sync(af[i], ap, AS_COLS);
            }
#pragma unroll
            for (int j = 0; j < FN; j++) {
                const __half* bp = B_COL
                    ? &Bs[(wn * WN + j * 16) * BS_COLS + kk]
                    : &Bs[kk * BS_COLS + wn * WN + j * 16];
                wmma::load_matrix_sync(bf[j], bp, BS_COLS);
            }
#pragma unroll
            for (int i = 0; i < FM; i++)
#pragma unroll
                for (int j = 0; j < FN; j++)
                    wmma::mma_sync(acc[i][j], af[i], bf[j], acc[i][j]);
        }
        __syncthreads();
    }

    // epilogue: stage each 16x16 frag through smem, apply alpha/exp/bias
    float* st = (float*)smem + wid * 256;
    int rr = lane >> 1, cc = (lane & 1) << 3;
#pragma unroll
    for (int i = 0; i < FM; i++)
#pragma unroll
        for (int j = 0; j < FN; j++) {
            wmma::store_matrix_sync(st, acc[i][j], 16, wmma::mem_row_major);
            __syncwarp();
            int grow = m0 + wm * WM + i * 16 + rr;
            int gcol = n0 + wn * WN + j * 16 + cc;
            float v[8];
#pragma unroll
            for (int t = 0; t < 8; t++) {
                float vv = st[rr * 16 + cc + t] * alpha;
                if (DOEXP) vv = __expf(vv);
                v[t] = vv;
            }
            if (BIAS) {
#pragma unroll
                for (int t = 0; t < 8; t++) v[t] += bias[gcol + t];
            }
            if (std::is_same<CT, __half>::value) {
                alignas(16) __half hv[8];
#pragma unroll
                for (int t = 0; t < 8; t++) hv[t] = __float2half(v[t]);
                *(int4*)((__half*)C + (size_t)grow * ldc + gcol) = *(int4*)hv;
            } else {
                float* dst = (float*)C + (size_t)grow * ldc + gcol;
                *(float4*)dst = make_float4(v[0], v[1], v[2], v[3]);
                *(float4*)(dst + 4) = make_float4(v[4], v[5], v[6], v[7]);
            }
            __syncwarp();
        }
}

struct GemmP { const __half* A; const __half* B; const float* bias; void* C; };

// projections: 4 problems, M=2048 N=1024 K=1024, C fp16; 4-stage BK=32 pipeline
// stage = (128*40 + 32*136)*2B = 18944B; x4 = 75776B dynamic (2 blocks/SM: regs cap)
#define PROJ_SMEM 75776
__global__ __launch_bounds__(256) void proj4_kernel(GemmP p0, GemmP p1, GemmP p2, GemmP p3) {
    extern __shared__ __align__(16) char dsmem[];
    GemmP g;
    switch (blockIdx.z) {
        case 0: g = p0; break;
        case 1: g = p1; break;
        case 2: g = p2; break;
        default: g = p3; break;
    }
    gemm_db<128, 128, 32, 64, 32, false, false, __half, false, false, 4>(
        g.A, INNER, g.B, INNER, nullptr, (__half*)g.C, INNER,
        DIM, 1.0f, blockIdx.y * 128, blockIdx.x * 128, dsmem);
}

// output projections: 2 problems, bias, C fp32 (into d_out); 4-stage
__global__ __launch_bounds__(256) void outproj2_kernel(GemmP p0, GemmP p1) {
    extern __shared__ __align__(16) char dsmem[];
    GemmP g = blockIdx.z ? p1 : p0;
    gemm_db<128, 128, 32, 64, 32, false, false, float, true, false, 4>(
        g.A, INNER, g.B, DIM, g.bias, (float*)g.C, DIM,
        INNER, 1.0f, blockIdx.y * 128, blockIdx.x * 128, dsmem);
}

// sim: E16 = exp(scale * qk @ cqk^T), K=64 (2 tiles), 2-stage
__global__ __launch_bounds__(256) void sim_wmma(const __half* __restrict__ QK,
                                                const __half* __restrict__ CQK,
                                                __half* __restrict__ E) {
    __shared__ __align__(16) char smem[40960];
    int bh = blockIdx.z;
    int b = bh >> 4, h = bh & 15;
    const __half* A = QK + (size_t)b * NN * INNER + h * DH;
    const __half* Bm = CQK + (size_t)b * NN * INNER + h * DH;
    __half* C = E + ((size_t)bh << 20);
    gemm_db<128, 128, 32, 64, 32, false, true, __half, false, true, 2>(
        A, INNER, Bm, INNER, nullptr, C, NN,
        DH, SCALE, blockIdx.y * 128, blockIdx.x * 128, smem);
}

// ---------------- fused row+col sums over fp16 E, one pass ----------------
// Block owns rows [r0, r0+64) of one bh, all 1024 cols.
// Thread (half = tid>>7, c8 = tid&127) reads int4 (8 cols) per row.
__global__ __launch_bounds__(256) void sums_kernel(const __half* __restrict__ E,
                                                   float* __restrict__ RS,
                                                   float* __restrict__ CS) {
    __shared__ float srow[64];
    __shared__ float scol[1024];
    int bh = blockIdx.y;
    int r0 = blockIdx.x * 64;
    int tid = threadIdx.x;
    int hf = tid >> 7;      // 0/1: rows r0+hf*32 .. +31
    int c8 = tid & 127;     // col group: cols c8*8 .. +7
    int lane = tid & 31;

    if (tid < 64) srow[tid] = 0.f;
    for (int t = tid; t < 1024; t += 256) scol[t] = 0.f;
    __syncthreads();

    const __half* base = E + ((size_t)bh << 20);
    float ca[8] = {0.f, 0.f, 0.f, 0.f, 0.f, 0.f, 0.f, 0.f};
    for (int rr = 0; rr < 32; rr++) {
        int row = r0 + hf * 32 + rr;
        int4 v = *(const int4*)(base + (size_t)row * NN + c8 * 8);
        const __half2* h2 = (const __half2*)&v;
        float rsum = 0.f;
#pragma unroll
        for (int k = 0; k < 4; k++) {
            float2 f = __half22float2(h2[k]);
            ca[2 * k] += f.x;
            ca[2 * k + 1] += f.y;
            rsum += f.x + f.y;
        }
        // all 32 lanes of this warp share the same row
#pragma unroll
        for (int off = 16; off; off >>= 1) rsum += __shfl_xor_sync(0xffffffffu, rsum, off);
        if (lane == 0) atomicAdd(&srow[hf * 32 + rr], rsum);
    }
#pragma unroll
    for (int k = 0; k < 8; k++) atomicAdd(&scol[c8 * 8 + k], ca[k]);
    __syncthreads();

    if (tid < 64) RS[bh * NN + r0 + tid] = srow[tid];  // block owns these rows
    for (int t = tid; t < 1024; t += 256) atomicAdd(&CS[bh * NN + t], scol[t]);
}

// ---------------- dual normalize + talking heads -> fp16 (reads fp16 E) --------
__global__ __launch_bounds__(256) void softmax_th(const __half* __restrict__ E,
                                                  const float* __restrict__ Wth,
                                                  const float* __restrict__ Wcth,
                                                  const float* __restrict__ RS,
                                                  const float* __restrict__ CS,
                                                  __half* __restrict__ ATT,
                                                  __half* __restrict__ CATT) {
    __shared__ float sW[256], sCW[256], srl[16];
    int b = blockIdx.z, i = blockIdx.y;
    int tid = threadIdx.x;
    int j = (blockIdx.x * 256 + tid) * 2;

    sW[tid] = Wth[tid];
    sCW[tid] = Wcth[tid];
    if (tid < 16) srl[tid] = 1.0f / RS[(b * 16 + tid) * NN + i];
    __syncthreads();

    float e0[16], e1[16], a0[16], a1[16];
#pragma unroll
    for (int h = 0; h < 16; h++) {
        __half2 f = *(const __half2*)&E[((size_t)(b * 16 + h) << 20) + (size_t)i * NN + j];
        e0[h] = __low2float(f);
        e1[h] = __high2float(f);
    }

    // row-normalized (attend over j)
#pragma unroll
    for (int h = 0; h < 16; h++) {
        a0[h] = e0[h] * srl[h];
        a1[h] = e1[h] * srl[h];
    }
#pragma unroll
    for (int g = 0; g < 16; g++) {
        float c0 = 0.f, c1 = 0.f;
#pragma unroll
        for (int h = 0; h < 16; h++) {
            float w = sW[g * 16 + h];
            c0 = fmaf(w, a0[h], c0);
            c1 = fmaf(w, a1[h], c1);
        }
        *(__half2*)&ATT[((size_t)(b * 16 + g) << 20) + (size_t)i * NN + j] =
            __floats2half2_rn(c0, c1);
    }

    // col-normalized (attend over i)
#pragma unroll
    for (int h = 0; h < 16; h++) {
        float2 cs = *(const float2*)&CS[(b * 16 + h) * NN + j];
        a0[h] = e0[h] * (1.0f / cs.x);
        a1[h] = e1[h] * (1.0f / cs.y);
    }
#pragma unroll
    for (int g = 0; g < 16; g++) {
        float c0 = 0.f, c1 = 0.f;
#pragma unroll
        for (int h = 0; h < 16; h++) {
            float w = sCW[g * 16 + h];
            c0 = fmaf(w, a0[h], c0);
            c1 = fmaf(w, a1[h], c1);
        }
        *(__half2*)&CATT[((size_t)(b * 16 + g) << 20) + (size_t)i * NN + j] =
            __floats2half2_rn(c0, c1);
    }
}

// ---------------- AV GEMMs (2-stage, unchanged tiling) ----------------
__global__ __launch_bounds__(256) void av_nn_wmma(const __half* __restrict__ ATT,
                                                  const __half* __restrict__ V,
                                                  __half* __restrict__ O) {
    __shared__ __align__(16) char smem[29696];
    int z = blockIdx.z;
    int b = z >> 4, g = z & 15;
    const __half* A = ATT + ((size_t)z << 20);
    const __half* Bm = V + ((size_t)b << 20) + g * DH;
    __half* C = O + ((size_t)b << 20) + g * DH;
    gemm_db<128, 64, 32, 32, 32, false, false, __half, false, false, 2>(
        A, NN, Bm, INNER, nullptr, C, INNER,
        NN, 1.0f, blockIdx.y * 128, 0, smem);
}

__global__ __launch_bounds__(256) void av_tn_wmma(const __half* __restrict__ CATT,
                                                  const __half* __restrict__ V,
                                                  __half* __restrict__ O) {
    __shared__ __align__(16) char smem[26624];
    int z = blockIdx.z;
    int b = z >> 4, g = z & 15;
    const __half* A = CATT + ((size_t)z << 20);
    const __half* Bm = V + ((size_t)b << 20) + g * DH;
    __half* C = O + ((size_t)b << 20) + g * DH;
    gemm_db<128, 64, 32, 32, 32, true, false, __half, false, false, 2>(
        A, NN, Bm, INNER, nullptr, C, INNER,
        NN, 1.0f, blockIdx.y * 128, 0, smem);
}

// ---------------- launch ----------------
extern "C" void kernel_launch(void* const* d_in, const int* in_sizes, int n_in,
                              void* d_out, int out_size) {
    const float* x = (const float*)d_in[0];
    const float* ctx = (const float*)d_in[1];
    const float* ln_g = (const float*)d_in[4];
    const float* ln_b = (const float*)d_in[5];
    const float* cln_g = (const float*)d_in[6];
    const float* cln_b = (const float*)d_in[7];
    const float* W_qk = (const float*)d_in[8];
    const float* W_cqk = (const float*)d_in[9];
    const float* W_v = (const float*)d_in[10];
    const float* W_cv = (const float*)d_in[11];
    const float* W_out = (const float*)d_in[12];
    const float* b_out = (const float*)d_in[13];
    const float* W_cout = (const float*)d_in[14];
    const float* b_cout = (const float*)d_in[15];
    const float* W_th = (const float*)d_in[16];
    const float* W_cth = (const float*)d_in[17];
    float* out = (float*)d_out;

    __half *xn16, *cn16, *wqk16, *wcqk16, *wv16, *wcv16, *wout16, *wcout16;
    __half *qk16, *cqk16, *v16, *cv16, *attn16, *cattn16, *o16, *co16, *E;
    float *rs, *cs;
    cudaGetSymbolAddress((void**)&xn16, g_xn16);
    cudaGetSymbolAddress((void**)&cn16, g_cn16);
    cudaGetSymbolAddress((void**)&wqk16, g_wqk16);
    cudaGetSymbolAddress((void**)&wcqk16, g_wcqk16);
    cudaGetSymbolAddress((void**)&wv16, g_wv16);
    cudaGetSymbolAddress((void**)&wcv16, g_wcv16);
    cudaGetSymbolAddress((void**)&wout16, g_wout16);
    cudaGetSymbolAddress((void**)&wcout16, g_wcout16);
    cudaGetSymbolAddress((void**)&qk16, g_qk16);
    cudaGetSymbolAddress((void**)&cqk16, g_cqk16);
    cudaGetSymbolAddress((void**)&v16, g_v16);
    cudaGetSymbolAddress((void**)&cv16, g_cv16);
    cudaGetSymbolAddress((void**)&attn16, g_attn16);
    cudaGetSymbolAddress((void**)&cattn16, g_cattn16);
    cudaGetSymbolAddress((void**)&o16, g_o16);
    cudaGetSymbolAddress((void**)&co16, g_co16);
    cudaGetSymbolAddress((void**)&E, g_E16);
    cudaGetSymbolAddress((void**)&rs, g_rs);
    cudaGetSymbolAddress((void**)&cs, g_cs);

    cudaFuncSetAttribute(proj4_kernel, cudaFuncAttributeMaxDynamicSharedMemorySize, PROJ_SMEM);
    cudaFuncSetAttribute(outproj2_kernel, cudaFuncAttributeMaxDynamicSharedMemorySize, PROJ_SMEM);

    // 1) LayerNorms (fp16 out) + weight conversions + CS zeroing
    ln_kernel<<<Bb * NN, 256>>>(x, ln_g, ln_b, xn16);
    ln_kernel<<<Bb * NN, 256>>>(ctx, cln_g, cln_b, cn16);
    {
        F2H6 p;
        p.s[0] = W_qk;   p.d[0] = wqk16;
        p.s[1] = W_cqk;  p.d[1] = wcqk16;
        p.s[2] = W_v;    p.d[2] = wv16;
        p.s[3] = W_cv;   p.d[3] = wcv16;
        p.s[4] = W_out;  p.d[4] = wout16;
        p.s[5] = W_cout; p.d[5] = wcout16;
        f2h6_kernel<<<6 * 1024, 256>>>(p);
    }
    zero_cs<<<32, 256>>>(cs);

    // 2) 4 input projections (4-stage pipeline)
    {
        GemmP p0 = {xn16, wqk16, nullptr, qk16};
        GemmP p1 = {cn16, wcqk16, nullptr, cqk16};
        GemmP p2 = {xn16, wv16, nullptr, v16};
        GemmP p3 = {cn16, wcv16, nullptr, cv16};
        proj4_kernel<<<dim3(8, 16, 4), 256, PROJ_SMEM>>>(p0, p1, p2, p3);
    }

    // 3) sim -> E16 = exp(scale*sim) (fp16)
    sim_wmma<<<dim3(8, 8, Bb * H), 256>>>(qk16, cqk16, E);

    // 4) fused row+col sums, single pass over E
    sums_kernel<<<dim3(16, Bb * H), 256>>>(E, rs, cs);

    // 5) dual normalize + talking heads (fp16 out)
    softmax_th<<<dim3(2, NN, Bb), 256>>>(E, W_th, W_cth, rs, cs, attn16, cattn16);

    // 6) AV products
    av_nn_wmma<<<dim3(1, 8, Bb * H), 256>>>(attn16, cv16, o16);
    av_tn_wmma<<<dim3(1, 8, Bb * H), 256>>>(cattn16, v16, co16);

    // 7) output projections (+bias) into d_out: [out | cout]
    {
        GemmP p0 = {o16, wout16, b_out, out};
        GemmP p1 = {co16, wcout16, b_cout, out + (size_t)Bb * NN * DIM};
        outproj2_kernel<<<dim3(8, 16, 2), 256, PROJ_SMEM>>>(p0, p1);
    }
}

// round 12
// speedup vs baseline: 1.5240x; 1.0389x over previous
#include <cuda_runtime.h>
#include <cuda_bf16.h>
#include <cuda_fp16.h>
#include <mma.h>
#include <math.h>
#include <cstdint>
#include <type_traits>

using namespace nvcuda;

#define Bb 2
#define NN 1024
#define DIM 1024
#define H 16
#define DH 64
#define INNER 1024
#define SCALE 0.125f

// ---------------- scratch (device globals; no allocation) ----------------
__device__ __half g_xn16[Bb * NN * DIM];
__device__ __half g_cn16[Bb * NN * DIM];
__device__ __half g_wqk16[DIM * INNER];
__device__ __half g_wcqk16[DIM * INNER];
__device__ __half g_wv16[DIM * INNER];
__device__ __half g_wcv16[DIM * INNER];
__device__ __half g_wout16[INNER * DIM];
__device__ __half g_wcout16[INNER * DIM];
__device__ __half g_qk16[Bb * NN * INNER];
__device__ __half g_cqk16[Bb * NN * INNER];
__device__ __half g_v16[Bb * NN * INNER];
__device__ __half g_cv16[Bb * NN * INNER];
__device__ __half g_E16[(size_t)Bb * H * NN * NN];       // 64 MB: exp(sim) fp16
__device__ __half g_attn16[(size_t)Bb * H * NN * NN];    // 64 MB
__device__ __half g_cattn16[(size_t)Bb * H * NN * NN];   // 64 MB
__device__ float g_rs[Bb * H * NN];                      // row sums of exp
__device__ float g_cs[Bb * H * NN];                      // col sums of exp
__device__ __half g_o16[Bb * NN * INNER];
__device__ __half g_co16[Bb * NN * INNER];

// ---------------- cp.async helpers ----------------
__device__ __forceinline__ void cpasync16(void* s, const void* g) {
    unsigned int sa = (unsigned int)__cvta_generic_to_shared(s);
    asm volatile("cp.async.cg.shared.global [%0], [%1], 16;\n" ::"r"(sa), "l"(g));
}
__device__ __forceinline__ void cpasync_commit() {
    asm volatile("cp.async.commit_group;\n" ::);
}
template <int N>
__device__ __forceinline__ void cpasync_wait() {
    asm volatile("cp.async.wait_group %0;\n" ::"n"(N));
}

// ------- fp32 -> fp16 conversion (6 weights) + CS zeroing, one launch -------
struct F2H6 { const float* s[6]; __half* d[6]; float* cs; };
__global__ __launch_bounds__(256) void f2h6_kernel(F2H6 p) {
    int which = blockIdx.x >> 10;
    if (which >= 6) {  // last 32 blocks zero CS (32768 floats)
        int i = ((blockIdx.x - 6144) * 256 + threadIdx.x) * 4;
        *(float4*)(p.cs + i) = make_float4(0.f, 0.f, 0.f, 0.f);
        return;
    }
    int i = ((blockIdx.x & 1023) * 256 + threadIdx.x) * 4;
    const float* s = p.s[which];
    __half* d = p.d[which];
    float4 f = *(const float4*)(s + i);
    *(__half2*)(d + i) = __floats2half2_rn(f.x, f.y);
    *(__half2*)(d + i + 2) = __floats2half2_rn(f.z, f.w);
}

// ---------------- LayerNorm -> fp16 (both tensors, one launch; z selects) --------
__global__ __launch_bounds__(256) void ln2_kernel(const float* __restrict__ X0,
                                                  const float* __restrict__ G0,
                                                  const float* __restrict__ B0,
                                                  __half* __restrict__ O0,
                                                  const float* __restrict__ X1,
                                                  const float* __restrict__ G1,
                                                  const float* __restrict__ B1,
                                                  __half* __restrict__ O1) {
    __shared__ float sred[8];
    __shared__ float sbc;
    const float* X = blockIdx.y ? X1 : X0;
    const float* G = blockIdx.y ? G1 : G0;
    const float* Bt = blockIdx.y ? B1 : B0;
    __half* O = blockIdx.y ? O1 : O0;

    int row = blockIdx.x;
    int tid = threadIdx.x;
    const float* x = X + (size_t)row * DIM;
    __half* o = O + (size_t)row * DIM;

    float v[4];
#pragma unroll
    for (int p = 0; p < 4; p++) v[p] = x[tid + 256 * p];

    float s = v[0] + v[1] + v[2] + v[3];
#pragma unroll
    for (int off = 16; off; off >>= 1) s += __shfl_xor_sync(0xffffffffu, s, off);
    int lane = tid & 31, w = tid >> 5;
    if (lane == 0) sred[w] = s;
    __syncthreads();
    if (tid == 0) {
        float t = 0.f;
#pragma unroll
        for (int k = 0; k < 8; k++) t += sred[k];
        sbc = t * (1.0f / DIM);
    }
    __syncthreads();
    float mu = sbc;
    __syncthreads();

    float d[4];
#pragma unroll
    for (int p = 0; p < 4; p++) d[p] = v[p] - mu;
    float s2 = d[0] * d[0] + d[1] * d[1] + d[2] * d[2] + d[3] * d[3];
#pragma unroll
    for (int off = 16; off; off >>= 1) s2 += __shfl_xor_sync(0xffffffffu, s2, off);
    if (lane == 0) sred[w] = s2;
    __syncthreads();
    if (tid == 0) {
        float t = 0.f;
#pragma unroll
        for (int k = 0; k < 8; k++) t += sred[k];
        sbc = rsqrtf(t * (1.0f / DIM) + 1e-5f);
    }
    __syncthreads();
    float rinv = sbc;

#pragma unroll
    for (int p = 0; p < 4; p++) {
        int idx = tid + 256 * p;
        o[idx] = __float2half(d[p] * rinv * G[idx] + Bt[idx]);
    }
}

// ---------------- multi-stage pipelined wmma GEMM block (fp16 in, fp32 acc) ----------
template <int BM, int BN, int BK, int WM, int WN,
          bool A_COL, bool B_COL, typename CT, bool BIAS, bool DOEXP, int STAGES>
__device__ __forceinline__ void gemm_db(
    const __half* __restrict__ A, int lda,
    const __half* __restrict__ B, int ldb,
    const float* __restrict__ bias,
    CT* __restrict__ C, int ldc,
    int K, float alpha, int m0, int n0, char* smem) {
    constexpr int AS_ROWS = A_COL ? BK : BM;
    constexpr int AS_COLS = (A_COL ? BM : BK) + 8;
    constexpr int BS_ROWS = B_COL ? BN : BK;
    constexpr int BS_COLS = (B_COL ? BK : BN) + 8;
    constexpr int A_ELE = AS_ROWS * AS_COLS;
    constexpr int B_ELE = BS_ROWS * BS_COLS;
    constexpr int STAGE = A_ELE + B_ELE;

    __half* sbase = (__half*)smem;

    constexpr int WARPS_N = BN / WN;
    constexpr int FM = WM / 16, FN = WN / 16;
    int tid = threadIdx.x;
    int wid = tid >> 5, lane = tid & 31;
    int wm = wid / WARPS_N, wn = wid % WARPS_N;

    wmma::fragment<wmma::accumulator, 16, 16, 16, float> acc[FM][FN];
#pragma unroll
    for (int i = 0; i < FM; i++)
#pragma unroll
        for (int j = 0; j < FN; j++) wmma::fill_fragment(acc[i][j], 0.0f);

    using ALay = typename std::conditional<A_COL, wmma::col_major, wmma::row_major>::type;
    using BLay = typename std::conditional<B_COL, wmma::col_major, wmma::row_major>::type;

    constexpr int AVEC = (A_COL ? BM : BK) / 8;
    constexpr int A_TOT = AS_ROWS * AVEC;
    constexpr int BVEC = (B_COL ? BK : BN) / 8;
    constexpr int B_TOT = BS_ROWS * BVEC;

    auto load_tile = [&](int k0, int buf) {
        __half* As = sbase + buf * STAGE;
        __half* Bs = As + A_ELE;
#pragma unroll
        for (int t = tid; t < A_TOT; t += 256) {
            int r = t / AVEC, c = (t % AVEC) * 8;
            const __half* src = A_COL
                ? A + (size_t)(k0 + r) * lda + m0 + c
                : A + (size_t)(m0 + r) * lda + k0 + c;
            cpasync16(&As[r * AS_COLS + c], src);
        }
#pragma unroll
        for (int t = tid; t < B_TOT; t += 256) {
            int r = t / BVEC, c = (t % BVEC) * 8;
            const __half* src = B_COL
                ? B + (size_t)(n0 + r) * ldb + k0 + c
                : B + (size_t)(k0 + r) * ldb + n0 + c;
            cpasync16(&Bs[r * BS_COLS + c], src);
        }
        cpasync_commit();
    };

    int KT = K / BK;
#pragma unroll
    for (int s = 0; s < STAGES - 1; s++) {
        if (s < KT) load_tile(s * BK, s);
        else cpasync_commit();
    }

    for (int kt = 0; kt < KT; kt++) {
        int nxt = kt + STAGES - 1;
        if (nxt < KT) load_tile(nxt * BK, nxt % STAGES);
        else cpasync_commit();
        cpasync_wait<STAGES - 1>();
        __syncthreads();

        __half* As = sbase + (kt % STAGES) * STAGE;
        __half* Bs = As + A_ELE;
#pragma unroll
        for (int kk = 0; kk < BK; kk += 16) {
            wmma::fragment<wmma::matrix_a, 16, 16, 16, __half, ALay> af[FM];
            wmma::fragment<wmma::matrix_b, 16, 16, 16, __half, BLay> bf[FN];
#pragma unroll
            for (int i = 0; i < FM; i++) {
                const __half* ap = A_COL
                    ? &As[kk * AS_COLS + wm * WM + i * 16]
                    : &As[(wm * WM + i * 16) * AS_COLS + kk];
                wmma::load_matrix_sync(af[i], ap, AS_COLS);
            }
#pragma unroll
            for (int j = 0; j < FN; j++) {
                const __half* bp = B_COL
                    ? &Bs[(wn * WN + j * 16) * BS_COLS + kk]
                    : &Bs[kk * BS_COLS + wn * WN + j * 16];
                wmma::load_matrix_sync(bf[j], bp, BS_COLS);
            }
#pragma unroll
            for (int i = 0; i < FM; i++)
#pragma unroll
                for (int j = 0; j < FN; j++)
                    wmma::mma_sync(acc[i][j], af[i], bf[j], acc[i][j]);
        }
        __syncthreads();
    }

    // epilogue: stage each 16x16 frag through smem, apply alpha/exp/bias
    float* st = (float*)smem + wid * 256;
    int rr = lane >> 1, cc = (lane & 1) << 3;
#pragma unroll
    for (int i = 0; i < FM; i++)
#pragma unroll
        for (int j = 0; j < FN; j++) {
            wmma::store_matrix_sync(st, acc[i][j], 16, wmma::mem_row_major);
            __syncwarp();
            int grow = m0 + wm * WM + i * 16 + rr;
            int gcol = n0 + wn * WN + j * 16 + cc;
            float v[8];
#pragma unroll
            for (int t = 0; t < 8; t++) {
                float vv = st[rr * 16 + cc + t] * alpha;
                if (DOEXP) vv = __expf(vv);
                v[t] = vv;
            }
            if (BIAS) {
#pragma unroll
                for (int t = 0; t < 8; t++) v[t] += bias[gcol + t];
            }
            if (std::is_same<CT, __half>::value) {
                alignas(16) __half hv[8];
#pragma unroll
                for (int t = 0; t < 8; t++) hv[t] = __float2half(v[t]);
                *(int4*)((__half*)C + (size_t)grow * ldc + gcol) = *(int4*)hv;
            } else {
                float* dst = (float*)C + (size_t)grow * ldc + gcol;
                *(float4*)dst = make_float4(v[0], v[1], v[2], v[3]);
                *(float4*)(dst + 4) = make_float4(v[4], v[5], v[6], v[7]);
            }
            __syncwarp();
        }
}

struct GemmP { const __half* A; const __half* B; const float* bias; void* C; };

// projections: 4 problems, M=2048 N=1024 K=1024, C fp16; 4-stage BK=32 pipeline
#define PROJ_SMEM 75776
__global__ __launch_bounds__(256) void proj4_kernel(GemmP p0, GemmP p1, GemmP p2, GemmP p3) {
    extern __shared__ __align__(16) char dsmem[];
    GemmP g;
    switch (blockIdx.z) {
        case 0: g = p0; break;
        case 1: g = p1; break;
        case 2: g = p2; break;
        default: g = p3; break;
    }
    gemm_db<128, 128, 32, 64, 32, false, false, __half, false, false, 4>(
        g.A, INNER, g.B, INNER, nullptr, (__half*)g.C, INNER,
        DIM, 1.0f, blockIdx.y * 128, blockIdx.x * 128, dsmem);
}

// output projections: 2 problems, bias, C fp32 (into d_out); 4-stage
__global__ __launch_bounds__(256) void outproj2_kernel(GemmP p0, GemmP p1) {
    extern __shared__ __align__(16) char dsmem[];
    GemmP g = blockIdx.z ? p1 : p0;
    gemm_db<128, 128, 32, 64, 32, false, false, float, true, false, 4>(
        g.A, INNER, g.B, DIM, g.bias, (float*)g.C, DIM,
        INNER, 1.0f, blockIdx.y * 128, blockIdx.x * 128, dsmem);
}

// sim: E16 = exp(scale * qk @ cqk^T), K=64 (2 tiles), 2-stage
__global__ __launch_bounds__(256) void sim_wmma(const __half* __restrict__ QK,
                                                const __half* __restrict__ CQK,
                                                __half* __restrict__ E) {
    __shared__ __align__(16) char smem[40960];
    int bh = blockIdx.z;
    int b = bh >> 4, h = bh & 15;
    const __half* A = QK + (size_t)b * NN * INNER + h * DH;
    const __half* Bm = CQK + (size_t)b * NN * INNER + h * DH;
    __half* C = E + ((size_t)bh << 20);
    gemm_db<128, 128, 32, 64, 32, false, true, __half, false, true, 2>(
        A, INNER, Bm, INNER, nullptr, C, NN,
        DH, SCALE, blockIdx.y * 128, blockIdx.x * 128, smem);
}

// ---------------- fused row+col sums over fp16 E, one pass ----------------
__global__ __launch_bounds__(256) void sums_kernel(const __half* __restrict__ E,
                                                   float* __restrict__ RS,
                                                   float* __restrict__ CS) {
    __shared__ float srow[64];
    __shared__ float scol[1024];
    int bh = blockIdx.y;
    int r0 = blockIdx.x * 64;
    int tid = threadIdx.x;
    int hf = tid >> 7;
    int c8 = tid & 127;
    int lane = tid & 31;

    if (tid < 64) srow[tid] = 0.f;
    for (int t = tid; t < 1024; t += 256) scol[t] = 0.f;
    __syncthreads();

    const __half* base = E + ((size_t)bh << 20);
    float ca[8] = {0.f, 0.f, 0.f, 0.f, 0.f, 0.f, 0.f, 0.f};
    for (int rr = 0; rr < 32; rr++) {
        int row = r0 + hf * 32 + rr;
        int4 v = *(const int4*)(base + (size_t)row * NN + c8 * 8);
        const __half2* h2 = (const __half2*)&v;
        float rsum = 0.f;
#pragma unroll
        for (int k = 0; k < 4; k++) {
            float2 f = __half22float2(h2[k]);
            ca[2 * k] += f.x;
            ca[2 * k + 1] += f.y;
            rsum += f.x + f.y;
        }
#pragma unroll
        for (int off = 16; off; off >>= 1) rsum += __shfl_xor_sync(0xffffffffu, rsum, off);
        if (lane == 0) atomicAdd(&srow[hf * 32 + rr], rsum);
    }
#pragma unroll
    for (int k = 0; k < 8; k++) atomicAdd(&scol[c8 * 8 + k], ca[k]);
    __syncthreads();

    if (tid < 64) RS[bh * NN + r0 + tid] = srow[tid];
    for (int t = tid; t < 1024; t += 256) atomicAdd(&CS[bh * NN + t], scol[t]);
}

// ---------------- dual normalize + talking heads -> fp16 (reads fp16 E) --------
__global__ __launch_bounds__(256) void softmax_th(const __half* __restrict__ E,
                                                  const float* __restrict__ Wth,
                                                  const float* __restrict__ Wcth,
                                                  const float* __restrict__ RS,
                                                  const float* __restrict__ CS,
                                                  __half* __restrict__ ATT,
                                                  __half* __restrict__ CATT) {
    __shared__ float sW[256], sCW[256], srl[16];
    int b = blockIdx.z, i = blockIdx.y;
    int tid = threadIdx.x;
    int j = (blockIdx.x * 256 + tid) * 2;

    sW[tid] = Wth[tid];
    sCW[tid] = Wcth[tid];
    if (tid < 16) srl[tid] = 1.0f / RS[(b * 16 + tid) * NN + i];
    __syncthreads();

    float e0[16], e1[16], a0[16], a1[16];
#pragma unroll
    for (int h = 0; h < 16; h++) {
        __half2 f = *(const __half2*)&E[((size_t)(b * 16 + h) << 20) + (size_t)i * NN + j];
        e0[h] = __low2float(f);
        e1[h] = __high2float(f);
    }

    // row-normalized (attend over j)
#pragma unroll
    for (int h = 0; h < 16; h++) {
        a0[h] = e0[h] * srl[h];
        a1[h] = e1[h] * srl[h];
    }
#pragma unroll
    for (int g = 0; g < 16; g++) {
        float c0 = 0.f, c1 = 0.f;
#pragma unroll
        for (int h = 0; h < 16; h++) {
            float w = sW[g * 16 + h];
            c0 = fmaf(w, a0[h], c0);
            c1 = fmaf(w, a1[h], c1);
        }
        *(__half2*)&ATT[((size_t)(b * 16 + g) << 20) + (size_t)i * NN + j] =
            __floats2half2_rn(c0, c1);
    }

    // col-normalized (attend over i)
#pragma unroll
    for (int h = 0; h < 16; h++) {
        float2 cs = *(const float2*)&CS[(b * 16 + h) * NN + j];
        a0[h] = e0[h] * (1.0f / cs.x);
        a1[h] = e1[h] * (1.0f / cs.y);
    }
#pragma unroll
    for (int g = 0; g < 16; g++) {
        float c0 = 0.f, c1 = 0.f;
#pragma unroll
        for (int h = 0; h < 16; h++) {
            float w = sCW[g * 16 + h];
            c0 = fmaf(w, a0[h], c0);
            c1 = fmaf(w, a1[h], c1);
        }
        *(__half2*)&CATT[((size_t)(b * 16 + g) << 20) + (size_t)i * NN + j] =
            __floats2half2_rn(c0, c1);
    }
}

// ---------------- AV GEMMs merged, 4-stage pipelines ----------------
// z<32: out = attn'@cv (row-major A). z>=32: cout = cattn'^T@v (col-major A).
// av_nn stage = (128*40 + 32*72)*2 = 14848 B; x4 = 59392 B dynamic.
#define AV_SMEM 59392
__global__ __launch_bounds__(256) void av_kernel(const __half* __restrict__ ATT,
                                                 const __half* __restrict__ CATT,
                                                 const __half* __restrict__ V,
                                                 const __half* __restrict__ CV,
                                                 __half* __restrict__ O,
                                                 __half* __restrict__ CO) {
    extern __shared__ __align__(16) char dsmem[];
    int z = blockIdx.z;
    if (z < 32) {
        int b = z >> 4, g = z & 15;
        gemm_db<128, 64, 32, 32, 32, false, false, __half, false, false, 4>(
            ATT + ((size_t)z << 20), NN, CV + ((size_t)b << 20) + g * DH, INNER,
            nullptr, O + ((size_t)b << 20) + g * DH, INNER,
            NN, 1.0f, blockIdx.y * 128, 0, dsmem);
    } else {
        int z2 = z - 32;
        int b = z2 >> 4, g = z2 & 15;
        gemm_db<128, 64, 32, 32, 32, true, false, __half, false, false, 4>(
            CATT + ((size_t)z2 << 20), NN, V + ((size_t)b << 20) + g * DH, INNER,
            nullptr, CO + ((size_t)b << 20) + g * DH, INNER,
            NN, 1.0f, blockIdx.y * 128, 0, dsmem);
    }
}

// ---------------- launch ----------------
extern "C" void kernel_launch(void* const* d_in, const int* in_sizes, int n_in,
                              void* d_out, int out_size) {
    const float* x = (const float*)d_in[0];
    const float* ctx = (const float*)d_in[1];
    const float* ln_g = (const float*)d_in[4];
    const float* ln_b = (const float*)d_in[5];
    const float* cln_g = (const float*)d_in[6];
    const float* cln_b = (const float*)d_in[7];
    const float* W_qk = (const float*)d_in[8];
    const float* W_cqk = (const float*)d_in[9];
    const float* W_v = (const float*)d_in[10];
    const float* W_cv = (const float*)d_in[11];
    const float* W_out = (const float*)d_in[12];
    const float* b_out = (const float*)d_in[13];
    const float* W_cout = (const float*)d_in[14];
    const float* b_cout = (const float*)d_in[15];
    const float* W_th = (const float*)d_in[16];
    const float* W_cth = (const float*)d_in[17];
    float* out = (float*)d_out;

    __half *xn16, *cn16, *wqk16, *wcqk16, *wv16, *wcv16, *wout16, *wcout16;
    __half *qk16, *cqk16, *v16, *cv16, *attn16, *cattn16, *o16, *co16, *E;
    float *rs, *cs;
    cudaGetSymbolAddress((void**)&xn16, g_xn16);
    cudaGetSymbolAddress((void**)&cn16, g_cn16);
    cudaGetSymbolAddress((void**)&wqk16, g_wqk16);
    cudaGetSymbolAddress((void**)&wcqk16, g_wcqk16);
    cudaGetSymbolAddress((void**)&wv16, g_wv16);
    cudaGetSymbolAddress((void**)&wcv16, g_wcv16);
    cudaGetSymbolAddress((void**)&wout16, g_wout16);
    cudaGetSymbolAddress((void**)&wcout16, g_wcout16);
    cudaGetSymbolAddress((void**)&qk16, g_qk16);
    cudaGetSymbolAddress((void**)&cqk16, g_cqk16);
    cudaGetSymbolAddress((void**)&v16, g_v16);
    cudaGetSymbolAddress((void**)&cv16, g_cv16);
    cudaGetSymbolAddress((void**)&attn16, g_attn16);
    cudaGetSymbolAddress((void**)&cattn16, g_cattn16);
    cudaGetSymbolAddress((void**)&o16, g_o16);
    cudaGetSymbolAddress((void**)&co16, g_co16);
    cudaGetSymbolAddress((void**)&E, g_E16);
    cudaGetSymbolAddress((void**)&rs, g_rs);
    cudaGetSymbolAddress((void**)&cs, g_cs);

    cudaFuncSetAttribute(proj4_kernel, cudaFuncAttributeMaxDynamicSharedMemorySize, PROJ_SMEM);
    cudaFuncSetAttribute(outproj2_kernel, cudaFuncAttributeMaxDynamicSharedMemorySize, PROJ_SMEM);
    cudaFuncSetAttribute(av_kernel, cudaFuncAttributeMaxDynamicSharedMemorySize, AV_SMEM);

    // 1) LayerNorms (both, one launch) + weight conversions + CS zeroing (one launch)
    ln2_kernel<<<dim3(Bb * NN, 2), 256>>>(x, ln_g, ln_b, xn16, ctx, cln_g, cln_b, cn16);
    {
        F2H6 p;
        p.s[0] = W_qk;   p.d[0] = wqk16;
        p.s[1] = W_cqk;  p.d[1] = wcqk16;
        p.s[2] = W_v;    p.d[2] = wv16;
        p.s[3] = W_cv;   p.d[3] = wcv16;
        p.s[4] = W_out;  p.d[4] = wout16;
        p.s[5] = W_cout; p.d[5] = wcout16;
        p.cs = cs;
        f2h6_kernel<<<6 * 1024 + 32, 256>>>(p);
    }

    // 2) 4 input projections (4-stage pipeline)
    {
        GemmP p0 = {xn16, wqk16, nullptr, qk16};
        GemmP p1 = {cn16, wcqk16, nullptr, cqk16};
        GemmP p2 = {xn16, wv16, nullptr, v16};
        GemmP p3 = {cn16, wcv16, nullptr, cv16};
        proj4_kernel<<<dim3(8, 16, 4), 256, PROJ_SMEM>>>(p0, p1, p2, p3);
    }

    // 3) sim -> E16 = exp(scale*sim) (fp16)
    sim_wmma<<<dim3(8, 8, Bb * H), 256>>>(qk16, cqk16, E);

    // 4) fused row+col sums, single pass over E
    sums_kernel<<<dim3(16, Bb * H), 256>>>(E, rs, cs);

    // 5) dual normalize + talking heads (fp16 out)
    softmax_th<<<dim3(2, NN, Bb), 256>>>(E, W_th, W_cth, rs, cs, attn16, cattn16);

    // 6) AV products (merged, 4-stage)
    av_kernel<<<dim3(1, 8, 64), 256, AV_SMEM>>>(attn16, cattn16, v16, cv16, o16, co16);

    // 7) output projections (+bias) into d_out: [out | cout]
    {
        GemmP p0 = {o16, wout16, b_out, out};
        GemmP p1 = {co16, wcout16, b_cout, out + (size_t)Bb * NN * DIM};
        outproj2_kernel<<<dim3(8, 16, 2), 256, PROJ_SMEM>>>(p0, p1);
    }
}